// round 5
// baseline (speedup 1.0000x reference)
#include <cuda_runtime.h>
#include <cstdint>

typedef unsigned long long u64;

#define HID 32
#define TSEQ 200
#define PSTEPS 50
#define BATCHN 32768

// ---------- packed f32x2 helpers (sm_103a) ----------
__device__ __forceinline__ u64 pack2(float a, float b) {
    u64 r; asm("mov.b64 %0, {%1, %2};" : "=l"(r) : "f"(a), "f"(b)); return r;
}
__device__ __forceinline__ void unpack2(u64 v, float& a, float& b) {
    asm("mov.b64 {%0, %1}, %2;" : "=f"(a), "=f"(b) : "l"(v));
}
__device__ __forceinline__ void fma2(u64& d, u64 a, u64 b) {
    asm("fma.rn.f32x2 %0, %1, %2, %0;" : "+l"(d) : "l"(a), "l"(b));
}
__device__ __forceinline__ u64 add2(u64 a, u64 b) {
    u64 r; asm("add.rn.f32x2 %0, %1, %2;" : "=l"(r) : "l"(a), "l"(b)); return r;
}
// LDS.128 (broadcast: all lanes same address -> 1 wavefront)
__device__ __forceinline__ void lds2(u64& a, u64& b, uint32_t addr) {
    asm volatile("ld.shared.v2.u64 {%0, %1}, [%2];" : "=l"(a), "=l"(b) : "r"(addr));
}

// ---------- fast activations ----------
__device__ __forceinline__ float fast_ex2(float x) {
    float r; asm("ex2.approx.f32 %0, %1;" : "=f"(r) : "f"(x)); return r;
}
__device__ __forceinline__ float fast_rcp(float x) {
    float r; asm("rcp.approx.f32 %0, %1;" : "=f"(r) : "f"(x)); return r;
}
__device__ __forceinline__ float sigm(float x) {
    return fast_rcp(1.0f + fast_ex2(-1.4426950408889634f * x));
}
__device__ __forceinline__ float tanh_(float x) {
    return fmaf(2.0f, fast_rcp(1.0f + fast_ex2(-2.8853900817779268f * x)), -1.0f);
}

// Compute this warp's 16 hidden units for this lane's sample.
// h[]   : full hidden state (ABS order), broadcast-packed pairs, registers
// c[]   : this warp's 16 cell states (registers)
// hnew[]: output, new h for own units
// All weight LDS addresses are warp-uniform -> broadcast, 1 wavefront each.
__device__ __forceinline__ void cell16(
    float x0, float x1, float x2, float x3,
    const u64 (&h)[HID], float (&c)[16], float (&hnew)[16],
    uint32_t bB, uint32_t bWih, uint32_t bWrow)
{
    const u64 xq0 = pack2(x0, x0), xq1 = pack2(x1, x1);
    const u64 xq2 = pack2(x2, x2), xq3 = pack2(x3, x3);

#pragma unroll
    for (int q = 0; q < 16; q++) {
        const uint32_t row = bWrow + (uint32_t)q * 512u;   // 32 quads * 16B per j
        u64 aif0, ago0;
        lds2(aif0, ago0, bB + (uint32_t)q * 16u);          // bias -> accumulators
        u64 aif1 = 0ull, ago1 = 0ull;

        // input contribution (4 dims)
        {
            u64 w0, w1;
            lds2(w0, w1, bWih + (uint32_t)q * 64u + 0u);
            fma2(aif0, w0, xq0); fma2(ago0, w1, xq0);
            lds2(w0, w1, bWih + (uint32_t)q * 64u + 16u);
            fma2(aif1, w0, xq1); fma2(ago1, w1, xq1);
            lds2(w0, w1, bWih + (uint32_t)q * 64u + 32u);
            fma2(aif0, w0, xq2); fma2(ago0, w1, xq2);
            lds2(w0, w1, bWih + (uint32_t)q * 64u + 48u);
            fma2(aif1, w0, xq3); fma2(ago1, w1, xq3);
        }

        // recurrent contribution: full 32-dim h (ABS order)
#pragma unroll
        for (int k = 0; k < HID; k += 2) {
            u64 u0, u1, u2, u3;
            lds2(u0, u1, row + (uint32_t)k * 16u);
            fma2(aif0, u0, h[k]);     fma2(ago0, u1, h[k]);
            lds2(u2, u3, row + (uint32_t)k * 16u + 16u);
            fma2(aif1, u2, h[k + 1]); fma2(ago1, u3, h[k + 1]);
        }

        u64 aif = add2(aif0, aif1);
        u64 ago = add2(ago0, ago1);
        float gi, gf, gg, go;
        unpack2(aif, gi, gf);
        unpack2(ago, gg, go);

        float si = sigm(gi);
        float tg = tanh_(gg);
        float so = sigm(go);
        float cn = fmaf(sigm(gf), c[q], si * tg);
        c[q] = cn;
        hnew[q] = so * tanh_(cn);
    }
}

__global__ void __launch_bounds__(64, 8) lstm_kernel(
    const float* __restrict__ hist,
    const float* __restrict__ Wih,
    const float* __restrict__ Whh,
    const float* __restrict__ bih,
    const float* __restrict__ bhh,
    const float* __restrict__ Wpred,
    const float* __restrict__ bpred,
    float* __restrict__ out)
{
    // gate-interleaved quads (Wi,Wf,Wg,Wo) per (j,k); no skew needed
    // (all lanes of a warp read the same address -> broadcast).
    __shared__ __align__(16) float sWhh[HID * HID * 4];   // 16 KB
    __shared__ __align__(16) float sWih[HID * 4 * 4];     // 2 KB
    __shared__ __align__(16) float sB[HID * 4];           // 512 B
    __shared__ __align__(16) float sWp[HID * 4];          // 512 B
    __shared__ float hBuf[2][HID][32];                    // 8 KB double-buffered h

    const int tid = threadIdx.x;

    // ---- pack weights into SMEM ----
    for (int idx = tid; idx < HID * HID; idx += 64) {
        int j = idx >> 5, k = idx & 31;
        sWhh[idx * 4 + 0] = Whh[(0 * HID + j) * HID + k];
        sWhh[idx * 4 + 1] = Whh[(1 * HID + j) * HID + k];
        sWhh[idx * 4 + 2] = Whh[(2 * HID + j) * HID + k];
        sWhh[idx * 4 + 3] = Whh[(3 * HID + j) * HID + k];
    }
    for (int idx = tid; idx < HID * 4; idx += 64) {
        int j = idx >> 2, d = idx & 3;
        sWih[idx * 4 + 0] = Wih[(0 * HID + j) * 4 + d];
        sWih[idx * 4 + 1] = Wih[(1 * HID + j) * 4 + d];
        sWih[idx * 4 + 2] = Wih[(2 * HID + j) * 4 + d];
        sWih[idx * 4 + 3] = Wih[(3 * HID + j) * 4 + d];
    }
    if (tid < HID) {
        int j = tid;
        sB[j * 4 + 0] = bih[0 * HID + j] + bhh[0 * HID + j];
        sB[j * 4 + 1] = bih[1 * HID + j] + bhh[1 * HID + j];
        sB[j * 4 + 2] = bih[2 * HID + j] + bhh[2 * HID + j];
        sB[j * 4 + 3] = bih[3 * HID + j] + bhh[3 * HID + j];
        // W_pred quad per k: (Wp0,Wp1,Wp2,Wp3)[k]
        sWp[j * 4 + 0] = Wpred[0 * HID + j];
        sWp[j * 4 + 1] = Wpred[1 * HID + j];
        sWp[j * 4 + 2] = Wpred[2 * HID + j];
        sWp[j * 4 + 3] = Wpred[3 * HID + j];
    }
    __syncthreads();

    const uint32_t aWhh = (uint32_t)__cvta_generic_to_shared(sWhh);
    const uint32_t aWih = (uint32_t)__cvta_generic_to_shared(sWih);
    const uint32_t aB   = (uint32_t)__cvta_generic_to_shared(sB);
    const uint32_t aWp  = (uint32_t)__cvta_generic_to_shared(sWp);

    const int lane  = tid & 31;            // sample within block
    const int wid   = tid >> 5;            // which 16 hidden units
    const int base  = wid * 16;            // own units  [base, base+16)
    const int pbase = 16 - base;           // partner units

    // warp-uniform bases into the weight arrays for own units
    const uint32_t bB    = aB   + (uint32_t)base * 16u;
    const uint32_t bWih  = aWih + (uint32_t)base * 64u;
    const uint32_t bWrow = aWhh + (uint32_t)base * 512u;

    const int b = blockIdx.x * 32 + lane;  // global sample
    const u64 bp01 = pack2(bpred[0], bpred[1]);
    const u64 bp23 = pack2(bpred[2], bpred[3]);

    u64 h[HID];
    float c[16], hnew[16];
#pragma unroll
    for (int k = 0; k < HID; k++) h[k] = 0ull;
#pragma unroll
    for (int q = 0; q < 16; q++) c[q] = 0.0f;

    int pb = 0;  // h double-buffer parity

    // ---- encoder: 200 steps ----
    const float4* xp = (const float4*)(hist + (size_t)b * (TSEQ * 4));
    for (int t = 0; t < TSEQ; t++) {
        float4 x = xp[t];
        cell16(x.x, x.y, x.z, x.w, h, c, hnew, bB, bWih, bWrow);

        // publish own units, then fetch partner's (one barrier per step;
        // double buffering removes the WAR hazard on the next iteration)
#pragma unroll
        for (int q = 0; q < 16; q++) hBuf[pb][base + q][lane] = hnew[q];
        __syncthreads();
#pragma unroll
        for (int q = 0; q < 16; q++) h[base + q] = pack2(hnew[q], hnew[q]);
#pragma unroll
        for (int q = 0; q < 16; q++) {
            float v = hBuf[pb][pbase + q][lane];
            h[pbase + q] = pack2(v, v);
        }
        pb ^= 1;
    }

    // ---- autoregressive decode: 50 steps (cell state reset each step) ----
    float4* op = (float4*)(out + (size_t)b * (PSTEPS * 4));
    for (int p = 0; p < PSTEPS; p++) {
        // pred = h @ W_pred^T + b_pred (both warps compute; they need it as x)
        u64 pr01 = bp01, pr23 = bp23;
#pragma unroll
        for (int k = 0; k < HID; k++) {
            u64 w01, w23;
            lds2(w01, w23, aWp + (uint32_t)k * 16u);
            fma2(pr01, w01, h[k]); fma2(pr23, w23, h[k]);
        }
        float p0, p1, p2, p3;
        unpack2(pr01, p0, p1);
        unpack2(pr23, p2, p3);
        if (wid == 0) op[p] = make_float4(p0, p1, p2, p3);

        // decode resets cell state each step
#pragma unroll
        for (int q = 0; q < 16; q++) c[q] = 0.0f;
        cell16(p0, p1, p2, p3, h, c, hnew, bB, bWih, bWrow);

#pragma unroll
        for (int q = 0; q < 16; q++) hBuf[pb][base + q][lane] = hnew[q];
        __syncthreads();
#pragma unroll
        for (int q = 0; q < 16; q++) h[base + q] = pack2(hnew[q], hnew[q]);
#pragma unroll
        for (int q = 0; q < 16; q++) {
            float v = hBuf[pb][pbase + q][lane];
            h[pbase + q] = pack2(v, v);
        }
        pb ^= 1;
    }
}

extern "C" void kernel_launch(void* const* d_in, const int* in_sizes, int n_in,
                              void* d_out, int out_size) {
    const float* hist  = (const float*)d_in[0];
    const float* Wih   = (const float*)d_in[1];
    const float* Whh   = (const float*)d_in[2];
    const float* bih   = (const float*)d_in[3];
    const float* bhh   = (const float*)d_in[4];
    const float* Wpred = (const float*)d_in[5];
    const float* bpred = (const float*)d_in[6];
    lstm_kernel<<<BATCHN / 32, 64>>>(hist, Wih, Whh, bih, bhh, Wpred, bpred,
                                     (float*)d_out);
}

// round 6
// speedup vs baseline: 1.0005x; 1.0005x over previous
#include <cuda_runtime.h>
#include <cstdint>

typedef unsigned long long u64;

#define HID 32
#define TSEQ 200
#define PSTEPS 50
#define BATCHN 32768

// ---------- packed f32x2 helpers (sm_103a) ----------
__device__ __forceinline__ u64 pack2(float a, float b) {
    u64 r; asm("mov.b64 %0, {%1, %2};" : "=l"(r) : "f"(a), "f"(b)); return r;
}
__device__ __forceinline__ void unpack2(u64 v, float& a, float& b) {
    asm("mov.b64 {%0, %1}, %2;" : "=f"(a), "=f"(b) : "l"(v));
}
__device__ __forceinline__ void fma2(u64& d, u64 a, u64 b) {
    asm("fma.rn.f32x2 %0, %1, %2, %0;" : "+l"(d) : "l"(a), "l"(b));
}
__device__ __forceinline__ u64 add2(u64 a, u64 b) {
    u64 r; asm("add.rn.f32x2 %0, %1, %2;" : "=l"(r) : "l"(a), "l"(b)); return r;
}
// LDS.128 (broadcast: all lanes same address -> 1 wavefront)
__device__ __forceinline__ void lds2(u64& a, u64& b, uint32_t addr) {
    asm volatile("ld.shared.v2.u64 {%0, %1}, [%2];" : "=l"(a), "=l"(b) : "r"(addr));
}

// ---------- fast activations ----------
__device__ __forceinline__ float fast_ex2(float x) {
    float r; asm("ex2.approx.f32 %0, %1;" : "=f"(r) : "f"(x)); return r;
}
__device__ __forceinline__ float fast_rcp(float x) {
    float r; asm("rcp.approx.f32 %0, %1;" : "=f"(r) : "f"(x)); return r;
}
__device__ __forceinline__ float sigm(float x) {
    return fast_rcp(1.0f + fast_ex2(-1.4426950408889634f * x));
}
__device__ __forceinline__ float tanh_(float x) {
    return fmaf(2.0f, fast_rcp(1.0f + fast_ex2(-2.8853900817779268f * x)), -1.0f);
}

// Compute this warp's 16 hidden units for this lane's sample.
// h[]   : full hidden state (ABS order), broadcast-packed pairs, registers
// c[]   : this warp's 16 cell states (registers)
// hnew[]: output, new h for own units
// All weight LDS addresses are warp-uniform -> broadcast, 1 wavefront each.
__device__ __forceinline__ void cell16(
    float x0, float x1, float x2, float x3,
    const u64 (&h)[HID], float (&c)[16], float (&hnew)[16],
    uint32_t bB, uint32_t bWih, uint32_t bWrow)
{
    const u64 xq0 = pack2(x0, x0), xq1 = pack2(x1, x1);
    const u64 xq2 = pack2(x2, x2), xq3 = pack2(x3, x3);

#pragma unroll
    for (int q = 0; q < 16; q++) {
        const uint32_t row = bWrow + (uint32_t)q * 512u;   // 32 quads * 16B per j
        u64 aif0, ago0;
        lds2(aif0, ago0, bB + (uint32_t)q * 16u);          // bias -> accumulators
        u64 aif1 = 0ull, ago1 = 0ull;

        // input contribution (4 dims)
        {
            u64 w0, w1;
            lds2(w0, w1, bWih + (uint32_t)q * 64u + 0u);
            fma2(aif0, w0, xq0); fma2(ago0, w1, xq0);
            lds2(w0, w1, bWih + (uint32_t)q * 64u + 16u);
            fma2(aif1, w0, xq1); fma2(ago1, w1, xq1);
            lds2(w0, w1, bWih + (uint32_t)q * 64u + 32u);
            fma2(aif0, w0, xq2); fma2(ago0, w1, xq2);
            lds2(w0, w1, bWih + (uint32_t)q * 64u + 48u);
            fma2(aif1, w0, xq3); fma2(ago1, w1, xq3);
        }

        // recurrent contribution: full 32-dim h (ABS order)
#pragma unroll
        for (int k = 0; k < HID; k += 2) {
            u64 u0, u1, u2, u3;
            lds2(u0, u1, row + (uint32_t)k * 16u);
            fma2(aif0, u0, h[k]);     fma2(ago0, u1, h[k]);
            lds2(u2, u3, row + (uint32_t)k * 16u + 16u);
            fma2(aif1, u2, h[k + 1]); fma2(ago1, u3, h[k + 1]);
        }

        u64 aif = add2(aif0, aif1);
        u64 ago = add2(ago0, ago1);
        float gi, gf, gg, go;
        unpack2(aif, gi, gf);
        unpack2(ago, gg, go);

        float si = sigm(gi);
        float tg = tanh_(gg);
        float so = sigm(go);
        float cn = fmaf(sigm(gf), c[q], si * tg);
        c[q] = cn;
        hnew[q] = so * tanh_(cn);
    }
}

__global__ void __launch_bounds__(64, 8) lstm_kernel(
    const float* __restrict__ hist,
    const float* __restrict__ Wih,
    const float* __restrict__ Whh,
    const float* __restrict__ bih,
    const float* __restrict__ bhh,
    const float* __restrict__ Wpred,
    const float* __restrict__ bpred,
    float* __restrict__ out)
{
    // gate-interleaved quads (Wi,Wf,Wg,Wo) per (j,k); no skew needed
    // (all lanes of a warp read the same address -> broadcast).
    __shared__ __align__(16) float sWhh[HID * HID * 4];   // 16 KB
    __shared__ __align__(16) float sWih[HID * 4 * 4];     // 2 KB
    __shared__ __align__(16) float sB[HID * 4];           // 512 B
    __shared__ __align__(16) float sWp[HID * 4];          // 512 B
    __shared__ float hBuf[2][HID][32];                    // 8 KB double-buffered h

    const int tid = threadIdx.x;

    // ---- pack weights into SMEM ----
    for (int idx = tid; idx < HID * HID; idx += 64) {
        int j = idx >> 5, k = idx & 31;
        sWhh[idx * 4 + 0] = Whh[(0 * HID + j) * HID + k];
        sWhh[idx * 4 + 1] = Whh[(1 * HID + j) * HID + k];
        sWhh[idx * 4 + 2] = Whh[(2 * HID + j) * HID + k];
        sWhh[idx * 4 + 3] = Whh[(3 * HID + j) * HID + k];
    }
    for (int idx = tid; idx < HID * 4; idx += 64) {
        int j = idx >> 2, d = idx & 3;
        sWih[idx * 4 + 0] = Wih[(0 * HID + j) * 4 + d];
        sWih[idx * 4 + 1] = Wih[(1 * HID + j) * 4 + d];
        sWih[idx * 4 + 2] = Wih[(2 * HID + j) * 4 + d];
        sWih[idx * 4 + 3] = Wih[(3 * HID + j) * 4 + d];
    }
    if (tid < HID) {
        int j = tid;
        sB[j * 4 + 0] = bih[0 * HID + j] + bhh[0 * HID + j];
        sB[j * 4 + 1] = bih[1 * HID + j] + bhh[1 * HID + j];
        sB[j * 4 + 2] = bih[2 * HID + j] + bhh[2 * HID + j];
        sB[j * 4 + 3] = bih[3 * HID + j] + bhh[3 * HID + j];
        // W_pred quad per k: (Wp0,Wp1,Wp2,Wp3)[k]
        sWp[j * 4 + 0] = Wpred[0 * HID + j];
        sWp[j * 4 + 1] = Wpred[1 * HID + j];
        sWp[j * 4 + 2] = Wpred[2 * HID + j];
        sWp[j * 4 + 3] = Wpred[3 * HID + j];
    }
    __syncthreads();

    const uint32_t aWhh = (uint32_t)__cvta_generic_to_shared(sWhh);
    const uint32_t aWih = (uint32_t)__cvta_generic_to_shared(sWih);
    const uint32_t aB   = (uint32_t)__cvta_generic_to_shared(sB);
    const uint32_t aWp  = (uint32_t)__cvta_generic_to_shared(sWp);

    const int lane  = tid & 31;            // sample within block
    const int wid   = tid >> 5;            // which 16 hidden units
    const int base  = wid * 16;            // own units  [base, base+16)
    const int pbase = 16 - base;           // partner units

    // warp-uniform bases into the weight arrays for own units
    const uint32_t bB    = aB   + (uint32_t)base * 16u;
    const uint32_t bWih  = aWih + (uint32_t)base * 64u;
    const uint32_t bWrow = aWhh + (uint32_t)base * 512u;

    const int b = blockIdx.x * 32 + lane;  // global sample
    const u64 bp01 = pack2(bpred[0], bpred[1]);
    const u64 bp23 = pack2(bpred[2], bpred[3]);

    u64 h[HID];
    float c[16], hnew[16];
#pragma unroll
    for (int k = 0; k < HID; k++) h[k] = 0ull;
#pragma unroll
    for (int q = 0; q < 16; q++) c[q] = 0.0f;

    int pb = 0;  // h double-buffer parity

    // ---- encoder: 200 steps ----
    const float4* xp = (const float4*)(hist + (size_t)b * (TSEQ * 4));
    for (int t = 0; t < TSEQ; t++) {
        float4 x = xp[t];
        cell16(x.x, x.y, x.z, x.w, h, c, hnew, bB, bWih, bWrow);

        // publish own units, then fetch partner's (one barrier per step;
        // double buffering removes the WAR hazard on the next iteration)
#pragma unroll
        for (int q = 0; q < 16; q++) hBuf[pb][base + q][lane] = hnew[q];
        __syncthreads();
#pragma unroll
        for (int q = 0; q < 16; q++) h[base + q] = pack2(hnew[q], hnew[q]);
#pragma unroll
        for (int q = 0; q < 16; q++) {
            float v = hBuf[pb][pbase + q][lane];
            h[pbase + q] = pack2(v, v);
        }
        pb ^= 1;
    }

    // ---- autoregressive decode: 50 steps (cell state reset each step) ----
    float4* op = (float4*)(out + (size_t)b * (PSTEPS * 4));
    for (int p = 0; p < PSTEPS; p++) {
        // pred = h @ W_pred^T + b_pred (both warps compute; they need it as x)
        u64 pr01 = bp01, pr23 = bp23;
#pragma unroll
        for (int k = 0; k < HID; k++) {
            u64 w01, w23;
            lds2(w01, w23, aWp + (uint32_t)k * 16u);
            fma2(pr01, w01, h[k]); fma2(pr23, w23, h[k]);
        }
        float p0, p1, p2, p3;
        unpack2(pr01, p0, p1);
        unpack2(pr23, p2, p3);
        if (wid == 0) op[p] = make_float4(p0, p1, p2, p3);

        // decode resets cell state each step
#pragma unroll
        for (int q = 0; q < 16; q++) c[q] = 0.0f;
        cell16(p0, p1, p2, p3, h, c, hnew, bB, bWih, bWrow);

#pragma unroll
        for (int q = 0; q < 16; q++) hBuf[pb][base + q][lane] = hnew[q];
        __syncthreads();
#pragma unroll
        for (int q = 0; q < 16; q++) h[base + q] = pack2(hnew[q], hnew[q]);
#pragma unroll
        for (int q = 0; q < 16; q++) {
            float v = hBuf[pb][pbase + q][lane];
            h[pbase + q] = pack2(v, v);
        }
        pb ^= 1;
    }
}

extern "C" void kernel_launch(void* const* d_in, const int* in_sizes, int n_in,
                              void* d_out, int out_size) {
    const float* hist  = (const float*)d_in[0];
    const float* Wih   = (const float*)d_in[1];
    const float* Whh   = (const float*)d_in[2];
    const float* bih   = (const float*)d_in[3];
    const float* bhh   = (const float*)d_in[4];
    const float* Wpred = (const float*)d_in[5];
    const float* bpred = (const float*)d_in[6];
    lstm_kernel<<<BATCHN / 32, 64>>>(hist, Wih, Whh, bih, bhh, Wpred, bpred,
                                     (float*)d_out);
}

// round 8
// speedup vs baseline: 2.1123x; 2.1113x over previous
#include <cuda_runtime.h>
#include <cuda_bf16.h>
#include <cstdint>

#define TSEQ 200
#define PSTEPS 50
#define BATCHN 32768
#define GSAMP 16
#define NCTA (BATCHN / GSAMP)   // 2048
#define XH_STR 40               // bf16 elems per row (80B, 16B aligned, conflict-free ldsm)
#define XX_STR 24               // 48B rows

// ---------------- helpers ----------------
__device__ __forceinline__ uint32_t s2u(const void* p) {
    uint32_t a;
    asm("{ .reg .u64 t; cvta.to.shared.u64 t, %1; cvt.u32.u64 %0, t; }" : "=r"(a) : "l"(p));
    return a;
}
__device__ __forceinline__ float fast_ex2(float x) {
    float r; asm("ex2.approx.f32 %0, %1;" : "=f"(r) : "f"(x)); return r;
}
__device__ __forceinline__ float fast_rcp(float x) {
    float r; asm("rcp.approx.f32 %0, %1;" : "=f"(r) : "f"(x)); return r;
}
__device__ __forceinline__ float sigm(float x) {
    return fast_rcp(1.0f + fast_ex2(-1.4426950408889634f * x));
}
__device__ __forceinline__ float tanh_(float x) {
    return fmaf(2.0f, fast_rcp(1.0f + fast_ex2(-2.8853900817779268f * x)), -1.0f);
}
__device__ __forceinline__ float bf_round(float a) {
    float r; asm("{.reg .b16 t; cvt.rn.bf16.f32 t, %1; cvt.f32.bf16 %0, t;}" : "=f"(r) : "f"(a));
    return r;
}
__device__ __forceinline__ uint32_t packbf(float a, float b) {
    uint32_t r;
    asm("{.reg .b16 x,y; cvt.rn.bf16.f32 x, %1; cvt.rn.bf16.f32 y, %2; mov.b32 %0, {x,y};}"
        : "=r"(r) : "f"(a), "f"(b));
    return r;
}
__device__ __forceinline__ void mma16816(float* d, const uint32_t* a, const uint32_t* b) {
    asm volatile("mma.sync.aligned.m16n8k16.row.col.f32.bf16.bf16.f32 "
                 "{%0,%1,%2,%3}, {%4,%5,%6,%7}, {%8,%9}, {%0,%1,%2,%3};"
                 : "+f"(d[0]), "+f"(d[1]), "+f"(d[2]), "+f"(d[3])
                 : "r"(a[0]), "r"(a[1]), "r"(a[2]), "r"(a[3]), "r"(b[0]), "r"(b[1]));
}
__device__ __forceinline__ void ldsm4(uint32_t* r, uint32_t addr) {
    asm volatile("ldmatrix.sync.aligned.m8n8.x4.shared.b16 {%0,%1,%2,%3}, [%4];"
                 : "=r"(r[0]), "=r"(r[1]), "=r"(r[2]), "=r"(r[3]) : "r"(addr));
}

// gate-column order within a unit: (i, o, f, g) -> original row blocks (0,3,1,2)*32
__device__ __forceinline__ int prow(int col) {
    int u = col >> 2, gs = col & 3;
    int blk = (gs == 0) ? 0 : (gs == 1) ? 3 : (gs == 2) ? 1 : 2;
    return blk * 32 + u;
}

__global__ void __launch_bounds__(128, 3) lstm_hmma_kernel(
    const float* __restrict__ hist,
    const float* __restrict__ Wih,
    const float* __restrict__ Whh,
    const float* __restrict__ bih,
    const float* __restrict__ bhh,
    const float* __restrict__ Wpred,
    const float* __restrict__ bpred,
    float* __restrict__ out)
{
    __shared__ __align__(16) __nv_bfloat16 Xhi[2][GSAMP][XH_STR];
    __shared__ __align__(16) __nv_bfloat16 Xlo[2][GSAMP][XH_STR];
    __shared__ __align__(16) __nv_bfloat16 Xx [2][GSAMP][XX_STR];

    const int tid  = threadIdx.x;
    const int lane = tid & 31;
    const int w    = tid >> 5;
    const int S0   = blockIdx.x * GSAMP;

    // ---------------- build B fragments in registers ----------------
    // B frag (m16n8k16 row.col): lane holds n = lane/4, k = {2(lane%3..)}:
    //   b0: k = 2j, 2j+1 ; b1: k = 2j+8, 2j+9   (j = lane&3)
    const int j    = lane & 3;
    const int nsub = lane >> 2;
    const int k0   = 2 * j;

    uint32_t Bh[4][2][2], Bl[4][2][2], Bx[4][2];
    uint32_t Ph[2][2], Pl[2][2], Px[2];   // warp3 pred tile (decode only)

#pragma unroll
    for (int t = 0; t < 4; t++) {
        int col = 32 * w + 8 * t + nsub;
        int pr  = prow(col);
#pragma unroll
        for (int c = 0; c < 2; c++) {
            int kb = c * 16;
            float w0 = Whh[pr * 32 + kb + k0],     w1 = Whh[pr * 32 + kb + k0 + 1];
            float w8 = Whh[pr * 32 + kb + k0 + 8], w9 = Whh[pr * 32 + kb + k0 + 9];
            Bh[t][c][0] = packbf(bf_round(w0), bf_round(w1));
            Bh[t][c][1] = packbf(bf_round(w8), bf_round(w9));
            Bl[t][c][0] = packbf(w0 - bf_round(w0), w1 - bf_round(w1));
            Bl[t][c][1] = packbf(w8 - bf_round(w8), w9 - bf_round(w9));
        }
        // x-chunk rows: 0-3 Uhi, 4-7 Uhi (pairs xlo), 8-11 Ulo, 12 b_hi, 13 b_lo
        float xv[4];
#pragma unroll
        for (int q = 0; q < 4; q++) {
            int k = ((q < 2) ? k0 : k0 + 8) + (q & 1);
            float v = 0.0f;
            if (k < 4)       v = bf_round(Wih[pr * 4 + k]);
            else if (k < 8)  v = bf_round(Wih[pr * 4 + k - 4]);
            else if (k < 12) { float u = Wih[pr * 4 + k - 8]; v = u - bf_round(u); }
            else if (k == 12) { float b = bih[pr] + bhh[pr]; v = bf_round(b); }
            else if (k == 13) { float b = bih[pr] + bhh[pr]; v = b - bf_round(b); }
            xv[q] = v;
        }
        Bx[t][0] = packbf(xv[0], xv[1]);
        Bx[t][1] = packbf(xv[2], xv[3]);
    }

    // ---------------- prime smem ----------------
    for (int i = tid; i < GSAMP * XH_STR; i += 128) {
        Xhi[0][i / XH_STR][i % XH_STR] = __float2bfloat16(0.0f);
        Xlo[0][i / XH_STR][i % XH_STR] = __float2bfloat16(0.0f);
    }
    if (tid < GSAMP) {
        const float4 x = ((const float4*)hist)[(size_t)(S0 + tid) * TSEQ];
        float h0 = bf_round(x.x), h1 = bf_round(x.y), h2 = bf_round(x.z), h3 = bf_round(x.w);
        uint4 q0, q1;
        q0.x = packbf(x.x, x.y);           q0.y = packbf(x.z, x.w);
        q0.z = packbf(x.x - h0, x.y - h1); q0.w = packbf(x.z - h2, x.w - h3);
        q1.x = q0.x; q1.y = q0.y;
        q1.z = packbf(1.0f, 1.0f);         q1.w = 0u;
        ((uint4*)&Xx[0][tid][0])[0] = q0;
        ((uint4*)&Xx[0][tid][0])[1] = q1;
    }
    __syncthreads();

    // ldmatrix addressing (x4): lane -> matrix m = lane/8
    const int mrow  = (lane & 7) + ((lane >> 3) & 1) * 8;
    const int mkoff = ((lane >> 4) & 1) * 16;      // bytes
    const uint32_t aXhi = s2u(&Xhi[0][0][0]);
    const uint32_t aXlo = s2u(&Xlo[0][0][0]);
    const uint32_t aXx  = s2u(&Xx[0][0][0]);
    const uint32_t PAR_H = GSAMP * XH_STR * 2;     // parity stride bytes
    const uint32_t PAR_X = GSAMP * XX_STR * 2;

    // epilogue constants: io lanes (j even): sigmoid; fg lanes (j odd): tanh
    const bool  isFG = (lane & 1);
    const float sA = isFG ? -2.8853900817779268f : -1.4426950408889634f;
    const float sB = isFG ? 2.0f : 1.0f;
    const float sC = isFG ? -1.0f : 0.0f;
    const int   r    = lane >> 2;                  // sample row (and r+8)
    const int   uown = 8 * w + ((lane >> 1) & 1);  // + 2*t later (fg lanes' unit)

    float cst[4][2];
#pragma unroll
    for (int t = 0; t < 4; t++) { cst[t][0] = 0.0f; cst[t][1] = 0.0f; }

    int p = 0;
    for (int step = 0; step < TSEQ + PSTEPS; step++) {
        const bool dec = (step >= TSEQ);

        // ---- decode boundary: rebuild B frags with fused weights ----
        if (step == TSEQ) {
#pragma unroll
            for (int t = 0; t < 4; t++) {
                int col = 32 * w + 8 * t + nsub;
                int pr  = prow(col);
#pragma unroll
                for (int c = 0; c < 2; c++) {
                    int kb = c * 16;
                    float wv[4];
#pragma unroll
                    for (int q = 0; q < 4; q++) {
                        int kk = kb + ((q < 2) ? k0 : k0 + 8) + (q & 1);
                        float v = Whh[pr * 32 + kk];
#pragma unroll
                        for (int d = 0; d < 4; d++)
                            v += Wih[pr * 4 + d] * Wpred[d * 32 + kk];
                        wv[q] = v;
                    }
                    Bh[t][c][0] = packbf(bf_round(wv[0]), bf_round(wv[1]));
                    Bh[t][c][1] = packbf(bf_round(wv[2]), bf_round(wv[3]));
                    Bl[t][c][0] = packbf(wv[0] - bf_round(wv[0]), wv[1] - bf_round(wv[1]));
                    Bl[t][c][1] = packbf(wv[2] - bf_round(wv[2]), wv[3] - bf_round(wv[3]));
                }
                float bd = bih[pr] + bhh[pr];
#pragma unroll
                for (int d = 0; d < 4; d++) bd += Wih[pr * 4 + d] * bpred[d];
                float xv[4];
#pragma unroll
                for (int q = 0; q < 4; q++) {
                    int k = ((q < 2) ? k0 : k0 + 8) + (q & 1);
                    xv[q] = (k == 12) ? bf_round(bd) : (k == 13) ? (bd - bf_round(bd)) : 0.0f;
                }
                Bx[t][0] = packbf(xv[0], xv[1]);
                Bx[t][1] = packbf(xv[2], xv[3]);
            }
            if (w == 3) {   // pred tile: cols = pred dims 0-3 (4-7 zero)
                int d = nsub;
                bool ok = (d < 4);
#pragma unroll
                for (int c = 0; c < 2; c++) {
                    int kb = c * 16;
                    float w0 = ok ? Wpred[d * 32 + kb + k0]     : 0.0f;
                    float w1 = ok ? Wpred[d * 32 + kb + k0 + 1] : 0.0f;
                    float w8 = ok ? Wpred[d * 32 + kb + k0 + 8] : 0.0f;
                    float w9 = ok ? Wpred[d * 32 + kb + k0 + 9] : 0.0f;
                    Ph[c][0] = packbf(bf_round(w0), bf_round(w1));
                    Ph[c][1] = packbf(bf_round(w8), bf_round(w9));
                    Pl[c][0] = packbf(w0 - bf_round(w0), w1 - bf_round(w1));
                    Pl[c][1] = packbf(w8 - bf_round(w8), w9 - bf_round(w9));
                }
                float bp = ok ? bpred[d] : 0.0f;
                float xv[4];
#pragma unroll
                for (int q = 0; q < 4; q++) {
                    int k = ((q < 2) ? k0 : k0 + 8) + (q & 1);
                    xv[q] = (k == 12) ? bf_round(bp) : (k == 13) ? (bp - bf_round(bp)) : 0.0f;
                }
                Px[0] = packbf(xv[0], xv[1]);
                Px[1] = packbf(xv[2], xv[3]);
            }
        }

        // ---- load A fragments from staging (parity p) ----
        uint32_t Ah0[4], Ah1[4], Al0[4], Al1[4], Ax[4];
        {
            uint32_t ah = aXhi + (uint32_t)p * PAR_H + (uint32_t)mrow * (XH_STR * 2) + mkoff;
            uint32_t al = aXlo + (uint32_t)p * PAR_H + (uint32_t)mrow * (XH_STR * 2) + mkoff;
            uint32_t ax = aXx  + (uint32_t)p * PAR_X + (uint32_t)mrow * (XX_STR * 2) + mkoff;
            ldsm4(Ah0, ah); ldsm4(Ah1, ah + 32);
            ldsm4(Al0, al); ldsm4(Al1, al + 32);
            ldsm4(Ax,  ax);
        }

        // ---- prefetch next encoder x ----
        float4 xn;
        const bool wantx = (!dec) && (step + 1 < TSEQ) && (w == 0) && (lane < GSAMP);
        if (wantx) xn = ((const float4*)hist)[(size_t)(S0 + lane) * TSEQ + step + 1];

        // ---- MMAs: G = Xhi*Whi + Xlo*Whi + Xhi*Wlo + Xx*Ux ----
        float dacc[4][4];
#pragma unroll
        for (int t = 0; t < 4; t++) {
#pragma unroll
            for (int e = 0; e < 4; e++) dacc[t][e] = 0.0f;
            mma16816(dacc[t], Ah0, Bh[t][0]); mma16816(dacc[t], Ah1, Bh[t][1]);
            mma16816(dacc[t], Al0, Bh[t][0]); mma16816(dacc[t], Al1, Bh[t][1]);
            mma16816(dacc[t], Ah0, Bl[t][0]); mma16816(dacc[t], Ah1, Bl[t][1]);
            mma16816(dacc[t], Ax,  Bx[t]);
        }
        if (dec && w == 3) {
            float dp[4] = {0.0f, 0.0f, 0.0f, 0.0f};
            mma16816(dp, Ah0, Ph[0]); mma16816(dp, Ah1, Ph[1]);
            mma16816(dp, Al0, Ph[0]); mma16816(dp, Al1, Ph[1]);
            mma16816(dp, Ah0, Pl[0]); mma16816(dp, Ah1, Pl[1]);
            mma16816(dp, Ax,  Px);
            if (j < 2) {   // lanes holding pred cols
                int ps = step - TSEQ;
                float2* o0 = (float2*)(out + (size_t)(S0 + r)     * (PSTEPS * 4) + ps * 4 + j * 2);
                float2* o1 = (float2*)(out + (size_t)(S0 + r + 8) * (PSTEPS * 4) + ps * 4 + j * 2);
                *o0 = make_float2(dp[0], dp[1]);
                *o1 = make_float2(dp[2], dp[3]);
            }
        }

        // ---- epilogue: activations + h staging (parity p^1) ----
#pragma unroll
        for (int t = 0; t < 4; t++) {
            // d0/d2: col 2j -> i (io lanes) or f (fg lanes): sigmoid both
            float v0r  = sigm(dacc[t][0]);
            float v0r8 = sigm(dacc[t][2]);
            // d1/d3: col 2j+1 -> o (sigm) or g (tanh): uniform instr, per-lane consts
            float v1r  = fmaf(sB, fast_rcp(1.0f + fast_ex2(sA * dacc[t][1])), sC);
            float v1r8 = fmaf(sB, fast_rcp(1.0f + fast_ex2(sA * dacc[t][3])), sC);
            // exchange with partner lane (io <-> fg)
            float siR  = __shfl_xor_sync(0xffffffffu, v0r,  1);
            float soR  = __shfl_xor_sync(0xffffffffu, v1r,  1);
            float siR8 = __shfl_xor_sync(0xffffffffu, v0r8, 1);
            float soR8 = __shfl_xor_sync(0xffffffffu, v1r8, 1);
            // fg lanes: v0 = sf, v1 = tg, recv si, so
            float cnR  = dec ? (siR  * v1r ) : fmaf(v0r,  cst[t][0], siR  * v1r );
            float cnR8 = dec ? (siR8 * v1r8) : fmaf(v0r8, cst[t][1], siR8 * v1r8);
            cst[t][0] = cnR;
            cst[t][1] = cnR8;
            float hR  = soR  * tanh_(cnR);
            float hR8 = soR8 * tanh_(cnR8);
            if (isFG) {
                int u = uown + 2 * t;
                Xhi[p ^ 1][r][u]     = __float2bfloat16(hR);
                Xhi[p ^ 1][r + 8][u] = __float2bfloat16(hR8);
                float hiR  = bf_round(hR),  hiR8 = bf_round(hR8);
                Xlo[p ^ 1][r][u]     = __float2bfloat16(hR - hiR);
                Xlo[p ^ 1][r + 8][u] = __float2bfloat16(hR8 - hiR8);
            }
        }

        if (wantx) {
            float h0 = bf_round(xn.x), h1 = bf_round(xn.y);
            float h2 = bf_round(xn.z), h3 = bf_round(xn.w);
            uint4 q0, q1;
            q0.x = packbf(xn.x, xn.y);           q0.y = packbf(xn.z, xn.w);
            q0.z = packbf(xn.x - h0, xn.y - h1); q0.w = packbf(xn.z - h2, xn.w - h3);
            q1.x = q0.x; q1.y = q0.y;
            q1.z = packbf(1.0f, 1.0f);           q1.w = 0u;
            ((uint4*)&Xx[p ^ 1][lane][0])[0] = q0;
            ((uint4*)&Xx[p ^ 1][lane][0])[1] = q1;
        }

        __syncthreads();
        p ^= 1;
    }
}

extern "C" void kernel_launch(void* const* d_in, const int* in_sizes, int n_in,
                              void* d_out, int out_size) {
    const float* hist  = (const float*)d_in[0];
    const float* Wih   = (const float*)d_in[1];
    const float* Whh   = (const float*)d_in[2];
    const float* bih   = (const float*)d_in[3];
    const float* bhh   = (const float*)d_in[4];
    const float* Wpred = (const float*)d_in[5];
    const float* bpred = (const float*)d_in[6];
    lstm_hmma_kernel<<<NCTA, 128>>>(hist, Wih, Whh, bih, bhh, Wpred, bpred,
                                    (float*)d_out);
}

// round 9
// speedup vs baseline: 4.3159x; 2.0432x over previous
#include <cuda_runtime.h>
#include <cuda_bf16.h>
#include <cstdint>

#define TSEQ 200
#define PSTEPS 50
#define BATCHN 32768
#define GSAMP 16
#define NCTA (BATCHN / GSAMP)   // 2048
#define XH_STR 40               // bf16 elems per row (80B, 16B aligned, conflict-free ldsm)
#define XX_STR 24               // 48B rows

// ---------------- helpers ----------------
__device__ __forceinline__ uint32_t s2u(const void* p) {
    uint32_t a;
    asm("{ .reg .u64 t; cvta.to.shared.u64 t, %1; cvt.u32.u64 %0, t; }" : "=r"(a) : "l"(p));
    return a;
}
__device__ __forceinline__ float tanhA(float x) {
    float r; asm("tanh.approx.f32 %0, %1;" : "=f"(r) : "f"(x)); return r;
}
__device__ __forceinline__ float sigmA(float x) {
    return fmaf(0.5f, tanhA(0.5f * x), 0.5f);
}
__device__ __forceinline__ float bf_round(float a) {
    float r; asm("{.reg .b16 t; cvt.rn.bf16.f32 t, %1; cvt.f32.bf16 %0, t;}" : "=f"(r) : "f"(a));
    return r;
}
__device__ __forceinline__ uint32_t packbf(float a, float b) {
    uint32_t r;
    asm("{.reg .b16 x,y; cvt.rn.bf16.f32 x, %1; cvt.rn.bf16.f32 y, %2; mov.b32 %0, {x,y};}"
        : "=r"(r) : "f"(a), "f"(b));
    return r;
}
__device__ __forceinline__ void mma16816(float* d, const uint32_t* a, const uint32_t* b) {
    asm volatile("mma.sync.aligned.m16n8k16.row.col.f32.bf16.bf16.f32 "
                 "{%0,%1,%2,%3}, {%4,%5,%6,%7}, {%8,%9}, {%0,%1,%2,%3};"
                 : "+f"(d[0]), "+f"(d[1]), "+f"(d[2]), "+f"(d[3])
                 : "r"(a[0]), "r"(a[1]), "r"(a[2]), "r"(a[3]), "r"(b[0]), "r"(b[1]));
}
__device__ __forceinline__ void ldsm4(uint32_t* r, uint32_t addr) {
    asm volatile("ldmatrix.sync.aligned.m8n8.x4.shared.b16 {%0,%1,%2,%3}, [%4];"
                 : "=r"(r[0]), "=r"(r[1]), "=r"(r[2]), "=r"(r[3]) : "r"(addr));
}

// Shuffle-free gate-column map. Global col (0..127) decodes to:
//   warp block = col>>5, tile t = (col>>3)&3, col-pair jc = (col>>1)&3, dj = col&1
//   unit u = 8*(col>>5) + jc + 4*(t>>1)
//   tile t even -> (i | f) by dj ; tile t odd -> (g | o) by dj
// so lane j's four dacc tiles hold complete (i,f,g,o) for units 8w+j and 8w+j+4.
__device__ __forceinline__ int prow(int col) {
    int t  = (col >> 3) & 3;
    int jc = (col >> 1) & 3;
    int dj = col & 1;
    int u  = ((col >> 5) << 3) + jc + ((t >> 1) << 2);
    int blk = (t & 1) ? (dj ? 3 : 2) : (dj ? 1 : 0);   // i,f,g,o row blocks
    return blk * 32 + u;
}

__global__ void __launch_bounds__(128, 4) lstm_hmma_kernel(
    const float* __restrict__ hist,
    const float* __restrict__ Wih,
    const float* __restrict__ Whh,
    const float* __restrict__ bih,
    const float* __restrict__ bhh,
    const float* __restrict__ Wpred,
    const float* __restrict__ bpred,
    float* __restrict__ out)
{
    __shared__ __align__(16) __nv_bfloat16 Xhi[2][GSAMP][XH_STR];
    __shared__ __align__(16) __nv_bfloat16 Xlo[2][GSAMP][XH_STR];
    __shared__ __align__(16) __nv_bfloat16 Xx [2][GSAMP][XX_STR];

    const int tid  = threadIdx.x;
    const int lane = tid & 31;
    const int w    = tid >> 5;
    const int S0   = blockIdx.x * GSAMP;

    // B frag (m16n8k16 row.col): lane holds n = lane>>2; b0: k = 2j,2j+1; b1: k+8
    const int j    = lane & 3;
    const int nsub = lane >> 2;
    const int k0   = 2 * j;

    uint32_t Bh[4][2][2], Bl[4][2][2], Bx[4][2];
    uint32_t Ph[2][2], Pl[2][2], Px[2];   // warp3 pred tile (decode only)

#pragma unroll
    for (int t = 0; t < 4; t++) {
        int col = 32 * w + 8 * t + nsub;
        int pr  = prow(col);
#pragma unroll
        for (int c = 0; c < 2; c++) {
            int kb = c * 16;
            float w0 = Whh[pr * 32 + kb + k0],     w1 = Whh[pr * 32 + kb + k0 + 1];
            float w8 = Whh[pr * 32 + kb + k0 + 8], w9 = Whh[pr * 32 + kb + k0 + 9];
            Bh[t][c][0] = packbf(bf_round(w0), bf_round(w1));
            Bh[t][c][1] = packbf(bf_round(w8), bf_round(w9));
            Bl[t][c][0] = packbf(w0 - bf_round(w0), w1 - bf_round(w1));
            Bl[t][c][1] = packbf(w8 - bf_round(w8), w9 - bf_round(w9));
        }
        // x-chunk rows: 0-3 Uhi, 4-7 Uhi (pairs xlo), 8-11 Ulo, 12 b_hi, 13 b_lo
        float xv[4];
#pragma unroll
        for (int q = 0; q < 4; q++) {
            int k = ((q < 2) ? k0 : k0 + 8) + (q & 1);
            float v = 0.0f;
            if (k < 4)       v = bf_round(Wih[pr * 4 + k]);
            else if (k < 8)  v = bf_round(Wih[pr * 4 + k - 4]);
            else if (k < 12) { float u = Wih[pr * 4 + k - 8]; v = u - bf_round(u); }
            else if (k == 12) { float b = bih[pr] + bhh[pr]; v = bf_round(b); }
            else if (k == 13) { float b = bih[pr] + bhh[pr]; v = b - bf_round(b); }
            xv[q] = v;
        }
        Bx[t][0] = packbf(xv[0], xv[1]);
        Bx[t][1] = packbf(xv[2], xv[3]);
    }

    // ---------------- prime smem ----------------
    for (int i = tid; i < GSAMP * XH_STR; i += 128) {
        Xhi[0][i / XH_STR][i % XH_STR] = __float2bfloat16(0.0f);
        Xlo[0][i / XH_STR][i % XH_STR] = __float2bfloat16(0.0f);
    }
    if (tid < GSAMP) {
        const float4 x = ((const float4*)hist)[(size_t)(S0 + tid) * TSEQ];
        float h0 = bf_round(x.x), h1 = bf_round(x.y), h2 = bf_round(x.z), h3 = bf_round(x.w);
        uint4 q0, q1;
        q0.x = packbf(x.x, x.y);           q0.y = packbf(x.z, x.w);
        q0.z = packbf(x.x - h0, x.y - h1); q0.w = packbf(x.z - h2, x.w - h3);
        q1.x = q0.x; q1.y = q0.y;
        q1.z = packbf(1.0f, 1.0f);         q1.w = 0u;
        ((uint4*)&Xx[0][tid][0])[0] = q0;
        ((uint4*)&Xx[0][tid][0])[1] = q1;
    }
    __syncthreads();

    // ldmatrix addressing (x4): lane -> matrix m = lane/8
    const int mrow  = (lane & 7) + ((lane >> 3) & 1) * 8;
    const int mkoff = ((lane >> 4) & 1) * 16;      // bytes
    const uint32_t aXhi = s2u(&Xhi[0][0][0]);
    const uint32_t aXlo = s2u(&Xlo[0][0][0]);
    const uint32_t aXx  = s2u(&Xx[0][0][0]);
    const uint32_t PAR_H = GSAMP * XH_STR * 2;     // parity stride bytes
    const uint32_t PAR_X = GSAMP * XX_STR * 2;

    const int r  = lane >> 2;                      // sample row (and r+8)
    const int u0 = 8 * w + j;                      // this lane's units
    const int u1 = u0 + 4;

    float cst[4];                                  // c for (u0,r),(u0,r+8),(u1,r),(u1,r+8)
#pragma unroll
    for (int q = 0; q < 4; q++) cst[q] = 0.0f;

    int p = 0;
    for (int step = 0; step < TSEQ + PSTEPS; step++) {
        const bool dec = (step >= TSEQ);

        // ---- decode boundary: rebuild B frags with fused weights ----
        if (step == TSEQ) {
#pragma unroll
            for (int t = 0; t < 4; t++) {
                int col = 32 * w + 8 * t + nsub;
                int pr  = prow(col);
#pragma unroll
                for (int c = 0; c < 2; c++) {
                    int kb = c * 16;
                    float wv[4];
#pragma unroll
                    for (int q = 0; q < 4; q++) {
                        int kk = kb + ((q < 2) ? k0 : k0 + 8) + (q & 1);
                        float v = Whh[pr * 32 + kk];
#pragma unroll
                        for (int d = 0; d < 4; d++)
                            v += Wih[pr * 4 + d] * Wpred[d * 32 + kk];
                        wv[q] = v;
                    }
                    Bh[t][c][0] = packbf(bf_round(wv[0]), bf_round(wv[1]));
                    Bh[t][c][1] = packbf(bf_round(wv[2]), bf_round(wv[3]));
                    Bl[t][c][0] = packbf(wv[0] - bf_round(wv[0]), wv[1] - bf_round(wv[1]));
                    Bl[t][c][1] = packbf(wv[2] - bf_round(wv[2]), wv[3] - bf_round(wv[3]));
                }
                float bd = bih[pr] + bhh[pr];
#pragma unroll
                for (int d = 0; d < 4; d++) bd += Wih[pr * 4 + d] * bpred[d];
                float xv[4];
#pragma unroll
                for (int q = 0; q < 4; q++) {
                    int k = ((q < 2) ? k0 : k0 + 8) + (q & 1);
                    xv[q] = (k == 12) ? bf_round(bd) : (k == 13) ? (bd - bf_round(bd)) : 0.0f;
                }
                Bx[t][0] = packbf(xv[0], xv[1]);
                Bx[t][1] = packbf(xv[2], xv[3]);
            }
            if (w == 3) {   // pred tile: cols = pred dims 0-3 (4-7 zero)
                int d = nsub;
                bool ok = (d < 4);
#pragma unroll
                for (int c = 0; c < 2; c++) {
                    int kb = c * 16;
                    float w0 = ok ? Wpred[d * 32 + kb + k0]     : 0.0f;
                    float w1 = ok ? Wpred[d * 32 + kb + k0 + 1] : 0.0f;
                    float w8 = ok ? Wpred[d * 32 + kb + k0 + 8] : 0.0f;
                    float w9 = ok ? Wpred[d * 32 + kb + k0 + 9] : 0.0f;
                    Ph[c][0] = packbf(bf_round(w0), bf_round(w1));
                    Ph[c][1] = packbf(bf_round(w8), bf_round(w9));
                    Pl[c][0] = packbf(w0 - bf_round(w0), w1 - bf_round(w1));
                    Pl[c][1] = packbf(w8 - bf_round(w8), w9 - bf_round(w9));
                }
                float bp = ok ? bpred[d] : 0.0f;
                float xv[4];
#pragma unroll
                for (int q = 0; q < 4; q++) {
                    int k = ((q < 2) ? k0 : k0 + 8) + (q & 1);
                    xv[q] = (k == 12) ? bf_round(bp) : (k == 13) ? (bp - bf_round(bp)) : 0.0f;
                }
                Px[0] = packbf(xv[0], xv[1]);
                Px[1] = packbf(xv[2], xv[3]);
            }
        }

        // ---- load A fragments from staging (parity p) ----
        uint32_t Ah0[4], Ah1[4], Al0[4], Al1[4], Ax[4];
        {
            uint32_t ah = aXhi + (uint32_t)p * PAR_H + (uint32_t)mrow * (XH_STR * 2) + mkoff;
            uint32_t al = aXlo + (uint32_t)p * PAR_H + (uint32_t)mrow * (XH_STR * 2) + mkoff;
            uint32_t ax = aXx  + (uint32_t)p * PAR_X + (uint32_t)mrow * (XX_STR * 2) + mkoff;
            ldsm4(Ah0, ah); ldsm4(Ah1, ah + 32);
            ldsm4(Al0, al); ldsm4(Al1, al + 32);
            ldsm4(Ax,  ax);
        }

        // ---- prefetch next encoder x ----
        float4 xn;
        const bool wantx = (!dec) && (step + 1 < TSEQ) && (w == 0) && (lane < GSAMP);
        if (wantx) xn = ((const float4*)hist)[(size_t)(S0 + lane) * TSEQ + step + 1];

        // ---- MMAs: G = Xhi*Whi + Xlo*Whi + Xhi*Wlo + Xx*Ux ----
        float dacc[4][4];
#pragma unroll
        for (int t = 0; t < 4; t++) {
#pragma unroll
            for (int e = 0; e < 4; e++) dacc[t][e] = 0.0f;
            mma16816(dacc[t], Ah0, Bh[t][0]); mma16816(dacc[t], Ah1, Bh[t][1]);
            mma16816(dacc[t], Al0, Bh[t][0]); mma16816(dacc[t], Al1, Bh[t][1]);
            mma16816(dacc[t], Ah0, Bl[t][0]); mma16816(dacc[t], Ah1, Bl[t][1]);
            mma16816(dacc[t], Ax,  Bx[t]);
        }
        if (dec && w == 3) {
            float dp[4] = {0.0f, 0.0f, 0.0f, 0.0f};
            mma16816(dp, Ah0, Ph[0]); mma16816(dp, Ah1, Ph[1]);
            mma16816(dp, Al0, Ph[0]); mma16816(dp, Al1, Ph[1]);
            mma16816(dp, Ah0, Pl[0]); mma16816(dp, Ah1, Pl[1]);
            mma16816(dp, Ax,  Px);
            if (j < 2) {   // lanes holding pred cols
                int ps = step - TSEQ;
                float2* o0 = (float2*)(out + (size_t)(S0 + r)     * (PSTEPS * 4) + ps * 4 + j * 2);
                float2* o1 = (float2*)(out + (size_t)(S0 + r + 8) * (PSTEPS * 4) + ps * 4 + j * 2);
                *o0 = make_float2(dp[0], dp[1]);
                *o1 = make_float2(dp[2], dp[3]);
            }
        }

        // ---- epilogue: shuffle-free, divergence-free activations ----
        // tiles 2u, 2u+1 hold (i,f) and (g,o) for unit u0/u1, rows r and r+8
        float hs[4];
#pragma unroll
        for (int uu = 0; uu < 2; uu++) {
#pragma unroll
            for (int rr = 0; rr < 2; rr++) {
                float gi = dacc[2 * uu][2 * rr + 0];
                float gf = dacc[2 * uu][2 * rr + 1];
                float gg = dacc[2 * uu + 1][2 * rr + 0];
                float go = dacc[2 * uu + 1][2 * rr + 1];
                float si = sigmA(gi);
                float tg = tanhA(gg);
                float so = sigmA(go);
                int ci = 2 * uu + rr;
                float cn = dec ? (si * tg) : fmaf(sigmA(gf), cst[ci], si * tg);
                cst[ci] = cn;
                hs[ci] = so * tanhA(cn);
            }
        }
        {
            float h0r = bf_round(hs[0]), h1r = bf_round(hs[1]);
            float h2r = bf_round(hs[2]), h3r = bf_round(hs[3]);
            Xhi[p ^ 1][r][u0]     = __float2bfloat16(hs[0]);
            Xhi[p ^ 1][r + 8][u0] = __float2bfloat16(hs[1]);
            Xhi[p ^ 1][r][u1]     = __float2bfloat16(hs[2]);
            Xhi[p ^ 1][r + 8][u1] = __float2bfloat16(hs[3]);
            Xlo[p ^ 1][r][u0]     = __float2bfloat16(hs[0] - h0r);
            Xlo[p ^ 1][r + 8][u0] = __float2bfloat16(hs[1] - h1r);
            Xlo[p ^ 1][r][u1]     = __float2bfloat16(hs[2] - h2r);
            Xlo[p ^ 1][r + 8][u1] = __float2bfloat16(hs[3] - h3r);
        }

        if (wantx) {
            float h0 = bf_round(xn.x), h1 = bf_round(xn.y);
            float h2 = bf_round(xn.z), h3 = bf_round(xn.w);
            uint4 q0, q1;
            q0.x = packbf(xn.x, xn.y);           q0.y = packbf(xn.z, xn.w);
            q0.z = packbf(xn.x - h0, xn.y - h1); q0.w = packbf(xn.z - h2, xn.w - h3);
            q1.x = q0.x; q1.y = q0.y;
            q1.z = packbf(1.0f, 1.0f);           q1.w = 0u;
            ((uint4*)&Xx[p ^ 1][lane][0])[0] = q0;
            ((uint4*)&Xx[p ^ 1][lane][0])[1] = q1;
        }

        __syncthreads();
        p ^= 1;
    }
}

extern "C" void kernel_launch(void* const* d_in, const int* in_sizes, int n_in,
                              void* d_out, int out_size) {
    const float* hist  = (const float*)d_in[0];
    const float* Wih   = (const float*)d_in[1];
    const float* Whh   = (const float*)d_in[2];
    const float* bih   = (const float*)d_in[3];
    const float* bhh   = (const float*)d_in[4];
    const float* Wpred = (const float*)d_in[5];
    const float* bpred = (const float*)d_in[6];
    lstm_hmma_kernel<<<NCTA, 128>>>(hist, Wih, Whh, bih, bhh, Wpred, bpred,
                                    (float*)d_out);
}

// round 10
// speedup vs baseline: 5.5393x; 1.2835x over previous
#include <cuda_runtime.h>
#include <cuda_fp16.h>
#include <cstdint>

#define TSEQ 200
#define PSTEPS 50
#define BATCHN 32768
#define GSAMP 16
#define NCTA (BATCHN / GSAMP)   // 2048
#define XH_STR 40               // f16 elems per row (80B, 16B aligned, conflict-free ldsm)
#define XX_STR 24               // 48B rows

// ---------------- helpers ----------------
__device__ __forceinline__ uint32_t s2u(const void* p) {
    uint32_t a;
    asm("{ .reg .u64 t; cvta.to.shared.u64 t, %1; cvt.u32.u64 %0, t; }" : "=r"(a) : "l"(p));
    return a;
}
__device__ __forceinline__ float tanhA(float x) {
    float r; asm("tanh.approx.f32 %0, %1;" : "=f"(r) : "f"(x)); return r;
}
__device__ __forceinline__ float sigmA(float x) {
    return fmaf(0.5f, tanhA(0.5f * x), 0.5f);
}
__device__ __forceinline__ float h_round(float a) {   // float -> f16(rn) -> float
    float r; asm("{.reg .b16 t; cvt.rn.f16.f32 t, %1; cvt.f32.f16 %0, t;}" : "=f"(r) : "f"(a));
    return r;
}
__device__ __forceinline__ uint32_t packh(float a, float b) {  // (f16(a), f16(b))
    uint32_t r;
    asm("{.reg .b16 x,y; cvt.rn.f16.f32 x, %1; cvt.rn.f16.f32 y, %2; mov.b32 %0, {x,y};}"
        : "=r"(r) : "f"(a), "f"(b));
    return r;
}
__device__ __forceinline__ void mma16816(float* d, const uint32_t* a, const uint32_t* b) {
    asm volatile("mma.sync.aligned.m16n8k16.row.col.f32.f16.f16.f32 "
                 "{%0,%1,%2,%3}, {%4,%5,%6,%7}, {%8,%9}, {%0,%1,%2,%3};"
                 : "+f"(d[0]), "+f"(d[1]), "+f"(d[2]), "+f"(d[3])
                 : "r"(a[0]), "r"(a[1]), "r"(a[2]), "r"(a[3]), "r"(b[0]), "r"(b[1]));
}
__device__ __forceinline__ void ldsm4(uint32_t* r, uint32_t addr) {
    asm volatile("ldmatrix.sync.aligned.m8n8.x4.shared.b16 {%0,%1,%2,%3}, [%4];"
                 : "=r"(r[0]), "=r"(r[1]), "=r"(r[2]), "=r"(r[3]) : "r"(addr));
}

// Shuffle-free gate-column map (same as R9): lane j's four dacc tiles hold
// complete (i,f,g,o) for units 8w+j and 8w+j+4, rows r and r+8.
__device__ __forceinline__ int prow(int col) {
    int t  = (col >> 3) & 3;
    int jc = (col >> 1) & 3;
    int dj = col & 1;
    int u  = ((col >> 5) << 3) + jc + ((t >> 1) << 2);
    int blk = (t & 1) ? (dj ? 3 : 2) : (dj ? 1 : 0);   // i,f,g,o row blocks
    return blk * 32 + u;
}

__global__ void __launch_bounds__(128, 5) lstm_hmma_kernel(
    const float* __restrict__ hist,
    const float* __restrict__ Wih,
    const float* __restrict__ Whh,
    const float* __restrict__ bih,
    const float* __restrict__ bhh,
    const float* __restrict__ Wpred,
    const float* __restrict__ bpred,
    float* __restrict__ out)
{
    __shared__ __align__(16) __half Xhi[2][GSAMP][XH_STR];
    __shared__ __align__(16) __half Xlo[2][GSAMP][XH_STR];
    __shared__ __align__(16) __half Xx [2][GSAMP][XX_STR];

    const int tid  = threadIdx.x;
    const int lane = tid & 31;
    const int w    = tid >> 5;
    const int S0   = blockIdx.x * GSAMP;

    // B frag (m16n8k16 row.col): lane holds n = lane>>2; b0: k = 2j,2j+1; b1: k+8
    const int j    = lane & 3;
    const int nsub = lane >> 2;
    const int k0   = 2 * j;

    uint32_t Bh[4][2][2], Bx[4][2];       // W in f16 (single term), x-chunk
    uint32_t Ph[2][2], Pl[2][2], Px[2];   // warp3 pred tile (decode; Wpred hi/lo)

#pragma unroll
    for (int t = 0; t < 4; t++) {
        int col = 32 * w + 8 * t + nsub;
        int pr  = prow(col);
#pragma unroll
        for (int c = 0; c < 2; c++) {
            int kb = c * 16;
            Bh[t][c][0] = packh(Whh[pr * 32 + kb + k0],     Whh[pr * 32 + kb + k0 + 1]);
            Bh[t][c][1] = packh(Whh[pr * 32 + kb + k0 + 8], Whh[pr * 32 + kb + k0 + 9]);
        }
        // x-chunk rows: 0-3 U (xhi), 4-7 U (xlo), 8-11 zero, 12 b_hi, 13 b_lo
        float xv[4];
#pragma unroll
        for (int q = 0; q < 4; q++) {
            int k = ((q < 2) ? k0 : k0 + 8) + (q & 1);
            float v = 0.0f;
            if (k < 4)       v = Wih[pr * 4 + k];
            else if (k < 8)  v = Wih[pr * 4 + k - 4];
            else if (k == 12) { float b = bih[pr] + bhh[pr]; v = h_round(b); }
            else if (k == 13) { float b = bih[pr] + bhh[pr]; v = b - h_round(b); }
            xv[q] = v;
        }
        Bx[t][0] = packh(xv[0], xv[1]);
        Bx[t][1] = packh(xv[2], xv[3]);
    }

    // ---------------- prime smem ----------------
    for (int i = tid; i < GSAMP * XH_STR; i += 128) {
        Xhi[0][i / XH_STR][i % XH_STR] = __float2half(0.0f);
        Xlo[0][i / XH_STR][i % XH_STR] = __float2half(0.0f);
    }
    if (tid < GSAMP) {
        const float4 x = ((const float4*)hist)[(size_t)(S0 + tid) * TSEQ];
        float h0 = h_round(x.x), h1 = h_round(x.y), h2 = h_round(x.z), h3 = h_round(x.w);
        uint4 q0, q1;
        q0.x = packh(x.x, x.y);           q0.y = packh(x.z, x.w);
        q0.z = packh(x.x - h0, x.y - h1); q0.w = packh(x.z - h2, x.w - h3);
        q1.x = 0u; q1.y = 0u;
        q1.z = packh(1.0f, 1.0f);         q1.w = 0u;
        ((uint4*)&Xx[0][tid][0])[0] = q0;
        ((uint4*)&Xx[0][tid][0])[1] = q1;
    }
    __syncthreads();

    // ldmatrix addressing (x4): lane -> matrix m = lane/8
    const int mrow  = (lane & 7) + ((lane >> 3) & 1) * 8;
    const int mkoff = ((lane >> 4) & 1) * 16;      // bytes
    const uint32_t aXhi = s2u(&Xhi[0][0][0]);
    const uint32_t aXlo = s2u(&Xlo[0][0][0]);
    const uint32_t aXx  = s2u(&Xx[0][0][0]);
    const uint32_t PAR_H = GSAMP * XH_STR * 2;     // parity stride bytes
    const uint32_t PAR_X = GSAMP * XX_STR * 2;

    const int r  = lane >> 2;                      // sample row (and r+8)
    const int u0 = 8 * w + j;                      // this lane's units
    const int u1 = u0 + 4;

    float cst[4];                                  // c for (u0,r),(u0,r+8),(u1,r),(u1,r+8)
#pragma unroll
    for (int q = 0; q < 4; q++) cst[q] = 0.0f;

    int p = 0;
    for (int step = 0; step < TSEQ + PSTEPS; step++) {
        const bool dec = (step >= TSEQ);

        // ---- decode boundary: rebuild B frags with fused weights ----
        if (step == TSEQ) {
#pragma unroll
            for (int t = 0; t < 4; t++) {
                int col = 32 * w + 8 * t + nsub;
                int pr  = prow(col);
#pragma unroll
                for (int c = 0; c < 2; c++) {
                    int kb = c * 16;
                    float wv[4];
#pragma unroll
                    for (int q = 0; q < 4; q++) {
                        int kk = kb + ((q < 2) ? k0 : k0 + 8) + (q & 1);
                        float v = Whh[pr * 32 + kk];
#pragma unroll
                        for (int d = 0; d < 4; d++)
                            v += Wih[pr * 4 + d] * Wpred[d * 32 + kk];
                        wv[q] = v;
                    }
                    Bh[t][c][0] = packh(wv[0], wv[1]);
                    Bh[t][c][1] = packh(wv[2], wv[3]);
                }
                float bd = bih[pr] + bhh[pr];
#pragma unroll
                for (int d = 0; d < 4; d++) bd += Wih[pr * 4 + d] * bpred[d];
                float xv[4];
#pragma unroll
                for (int q = 0; q < 4; q++) {
                    int k = ((q < 2) ? k0 : k0 + 8) + (q & 1);
                    xv[q] = (k == 12) ? h_round(bd) : (k == 13) ? (bd - h_round(bd)) : 0.0f;
                }
                Bx[t][0] = packh(xv[0], xv[1]);
                Bx[t][1] = packh(xv[2], xv[3]);
            }
            if (w == 3) {   // pred tile: cols = pred dims 0-3 (4-7 zero), Wpred hi/lo
                int d = nsub;
                bool ok = (d < 4);
#pragma unroll
                for (int c = 0; c < 2; c++) {
                    int kb = c * 16;
                    float w0 = ok ? Wpred[d * 32 + kb + k0]     : 0.0f;
                    float w1 = ok ? Wpred[d * 32 + kb + k0 + 1] : 0.0f;
                    float w8 = ok ? Wpred[d * 32 + kb + k0 + 8] : 0.0f;
                    float w9 = ok ? Wpred[d * 32 + kb + k0 + 9] : 0.0f;
                    Ph[c][0] = packh(w0, w1);
                    Ph[c][1] = packh(w8, w9);
                    Pl[c][0] = packh(w0 - h_round(w0), w1 - h_round(w1));
                    Pl[c][1] = packh(w8 - h_round(w8), w9 - h_round(w9));
                }
                float bp = ok ? bpred[d] : 0.0f;
                float xv[4];
#pragma unroll
                for (int q = 0; q < 4; q++) {
                    int k = ((q < 2) ? k0 : k0 + 8) + (q & 1);
                    xv[q] = (k == 12) ? h_round(bp) : (k == 13) ? (bp - h_round(bp)) : 0.0f;
                }
                Px[0] = packh(xv[0], xv[1]);
                Px[1] = packh(xv[2], xv[3]);
            }
        }

        // ---- load A fragments from staging (parity p) ----
        uint32_t Ah0[4], Ah1[4], Al0[4], Al1[4], Ax[4];
        {
            uint32_t ah = aXhi + (uint32_t)p * PAR_H + (uint32_t)mrow * (XH_STR * 2) + mkoff;
            uint32_t al = aXlo + (uint32_t)p * PAR_H + (uint32_t)mrow * (XH_STR * 2) + mkoff;
            uint32_t ax = aXx  + (uint32_t)p * PAR_X + (uint32_t)mrow * (XX_STR * 2) + mkoff;
            ldsm4(Ah0, ah); ldsm4(Ah1, ah + 32);
            ldsm4(Al0, al); ldsm4(Al1, al + 32);
            ldsm4(Ax,  ax);
        }

        // ---- prefetch next encoder x ----
        float4 xn;
        const bool wantx = (!dec) && (step + 1 < TSEQ) && (w == 0) && (lane < GSAMP);
        if (wantx) xn = ((const float4*)hist)[(size_t)(S0 + lane) * TSEQ + step + 1];

        // ---- MMAs: G = (h_hi + h_lo)*W + x-chunk   (5 per tile) ----
        float dacc[4][4];
#pragma unroll
        for (int t = 0; t < 4; t++) {
#pragma unroll
            for (int e = 0; e < 4; e++) dacc[t][e] = 0.0f;
            mma16816(dacc[t], Ah0, Bh[t][0]); mma16816(dacc[t], Ah1, Bh[t][1]);
            mma16816(dacc[t], Al0, Bh[t][0]); mma16816(dacc[t], Al1, Bh[t][1]);
            mma16816(dacc[t], Ax,  Bx[t]);
        }
        if (dec && w == 3) {
            float dp[4] = {0.0f, 0.0f, 0.0f, 0.0f};
            mma16816(dp, Ah0, Ph[0]); mma16816(dp, Ah1, Ph[1]);
            mma16816(dp, Al0, Ph[0]); mma16816(dp, Al1, Ph[1]);
            mma16816(dp, Ah0, Pl[0]); mma16816(dp, Ah1, Pl[1]);
            mma16816(dp, Ax,  Px);
            if (j < 2) {   // lanes holding pred cols
                int ps = step - TSEQ;
                float2* o0 = (float2*)(out + (size_t)(S0 + r)     * (PSTEPS * 4) + ps * 4 + j * 2);
                float2* o1 = (float2*)(out + (size_t)(S0 + r + 8) * (PSTEPS * 4) + ps * 4 + j * 2);
                *o0 = make_float2(dp[0], dp[1]);
                *o1 = make_float2(dp[2], dp[3]);
            }
        }

        // ---- epilogue: shuffle-free, divergence-free activations ----
        float hs[4];
#pragma unroll
        for (int uu = 0; uu < 2; uu++) {
#pragma unroll
            for (int rr = 0; rr < 2; rr++) {
                float gi = dacc[2 * uu][2 * rr + 0];
                float gf = dacc[2 * uu][2 * rr + 1];
                float gg = dacc[2 * uu + 1][2 * rr + 0];
                float go = dacc[2 * uu + 1][2 * rr + 1];
                float si = sigmA(gi);
                float tg = tanhA(gg);
                float so = sigmA(go);
                int ci = 2 * uu + rr;
                float cn = dec ? (si * tg) : fmaf(sigmA(gf), cst[ci], si * tg);
                cst[ci] = cn;
                hs[ci] = so * tanhA(cn);
            }
        }
        {
            float h0r = h_round(hs[0]), h1r = h_round(hs[1]);
            float h2r = h_round(hs[2]), h3r = h_round(hs[3]);
            Xhi[p ^ 1][r][u0]     = __float2half_rn(hs[0]);
            Xhi[p ^ 1][r + 8][u0] = __float2half_rn(hs[1]);
            Xhi[p ^ 1][r][u1]     = __float2half_rn(hs[2]);
            Xhi[p ^ 1][r + 8][u1] = __float2half_rn(hs[3]);
            Xlo[p ^ 1][r][u0]     = __float2half_rn(hs[0] - h0r);
            Xlo[p ^ 1][r + 8][u0] = __float2half_rn(hs[1] - h1r);
            Xlo[p ^ 1][r][u1]     = __float2half_rn(hs[2] - h2r);
            Xlo[p ^ 1][r + 8][u1] = __float2half_rn(hs[3] - h3r);
        }

        if (wantx) {
            float h0 = h_round(xn.x), h1 = h_round(xn.y);
            float h2 = h_round(xn.z), h3 = h_round(xn.w);
            uint4 q0, q1;
            q0.x = packh(xn.x, xn.y);           q0.y = packh(xn.z, xn.w);
            q0.z = packh(xn.x - h0, xn.y - h1); q0.w = packh(xn.z - h2, xn.w - h3);
            q1.x = 0u; q1.y = 0u;
            q1.z = packh(1.0f, 1.0f);           q1.w = 0u;
            ((uint4*)&Xx[p ^ 1][lane][0])[0] = q0;
            ((uint4*)&Xx[p ^ 1][lane][0])[1] = q1;
        }

        __syncthreads();
        p ^= 1;
    }
}

extern "C" void kernel_launch(void* const* d_in, const int* in_sizes, int n_in,
                              void* d_out, int out_size) {
    const float* hist  = (const float*)d_in[0];
    const float* Wih   = (const float*)d_in[1];
    const float* Whh   = (const float*)d_in[2];
    const float* bih   = (const float*)d_in[3];
    const float* bhh   = (const float*)d_in[4];
    const float* Wpred = (const float*)d_in[5];
    const float* bpred = (const float*)d_in[6];
    lstm_hmma_kernel<<<NCTA, 128>>>(hist, Wih, Whh, bih, bhh, Wpred, bpred,
                                    (float*)d_out);
}

// round 11
// speedup vs baseline: 6.6357x; 1.1979x over previous
#include <cuda_runtime.h>
#include <cuda_fp16.h>
#include <cstdint>

#define TSEQ 200
#define PSTEPS 50
#define BATCHN 32768
#define GSAMP 16
#define NCTA (BATCHN / GSAMP)   // 2048
#define XH_STR 40               // f16 elems per row (80B, 16B aligned, conflict-free ldsm)
#define XX_STR 24               // 48B rows

// ---------------- helpers ----------------
__device__ __forceinline__ uint32_t s2u(const void* p) {
    uint32_t a;
    asm("{ .reg .u64 t; cvta.to.shared.u64 t, %1; cvt.u32.u64 %0, t; }" : "=r"(a) : "l"(p));
    return a;
}
__device__ __forceinline__ float tanhA(float x) {
    float r; asm("tanh.approx.f32 %0, %1;" : "=f"(r) : "f"(x)); return r;
}
__device__ __forceinline__ float sigmA(float x) {
    return fmaf(0.5f, tanhA(0.5f * x), 0.5f);
}
__device__ __forceinline__ float h_round(float a) {   // float -> f16(rn) -> float
    float r; asm("{.reg .b16 t; cvt.rn.f16.f32 t, %1; cvt.f32.f16 %0, t;}" : "=f"(r) : "f"(a));
    return r;
}
__device__ __forceinline__ uint32_t packh(float a, float b) {  // (f16(a), f16(b))
    uint32_t r;
    asm("{.reg .b16 x,y; cvt.rn.f16.f32 x, %1; cvt.rn.f16.f32 y, %2; mov.b32 %0, {x,y};}"
        : "=r"(r) : "f"(a), "f"(b));
    return r;
}
__device__ __forceinline__ void mma16816(float* d, const uint32_t* a, const uint32_t* b) {
    asm volatile("mma.sync.aligned.m16n8k16.row.col.f32.f16.f16.f32 "
                 "{%0,%1,%2,%3}, {%4,%5,%6,%7}, {%8,%9}, {%0,%1,%2,%3};"
                 : "+f"(d[0]), "+f"(d[1]), "+f"(d[2]), "+f"(d[3])
                 : "r"(a[0]), "r"(a[1]), "r"(a[2]), "r"(a[3]), "r"(b[0]), "r"(b[1]));
}
__device__ __forceinline__ void ldsm4(uint32_t* r, uint32_t addr) {
    asm volatile("ldmatrix.sync.aligned.m8n8.x4.shared.b16 {%0,%1,%2,%3}, [%4];"
                 : "=r"(r[0]), "=r"(r[1]), "=r"(r[2]), "=r"(r[3]) : "r"(addr));
}

// Shuffle-free gate-column map (same as R9/R10): lane j's four dacc tiles hold
// complete (i,f,g,o) for units 8w+j and 8w+j+4, rows r and r+8.
__device__ __forceinline__ int prow(int col) {
    int t  = (col >> 3) & 3;
    int jc = (col >> 1) & 3;
    int dj = col & 1;
    int u  = ((col >> 5) << 3) + jc + ((t >> 1) << 2);
    int blk = (t & 1) ? (dj ? 3 : 2) : (dj ? 1 : 0);   // i,f,g,o row blocks
    return blk * 32 + u;
}

__global__ void __launch_bounds__(128, 6) lstm_hmma_kernel(
    const float* __restrict__ hist,
    const float* __restrict__ Wih,
    const float* __restrict__ Whh,
    const float* __restrict__ bih,
    const float* __restrict__ bhh,
    const float* __restrict__ Wpred,
    const float* __restrict__ bpred,
    float* __restrict__ out)
{
    __shared__ __align__(16) __half Xhi[2][GSAMP][XH_STR];
    __shared__ __align__(16) __half Xx [2][GSAMP][XX_STR];

    const int tid  = threadIdx.x;
    const int lane = tid & 31;
    const int w    = tid >> 5;
    const int S0   = blockIdx.x * GSAMP;

    // B frag (m16n8k16 row.col): lane holds n = lane>>2; b0: k = 2j,2j+1; b1: k+8
    const int j    = lane & 3;
    const int nsub = lane >> 2;
    const int k0   = 2 * j;

    uint32_t Bh[4][2][2], Bx[4][2];       // W in f16 (single term), x-chunk
    uint32_t Ph[2][2], Pl[2][2], Px[2];   // warp3 pred tile (decode; Wpred hi/lo)

#pragma unroll
    for (int t = 0; t < 4; t++) {
        int col = 32 * w + 8 * t + nsub;
        int pr  = prow(col);
#pragma unroll
        for (int c = 0; c < 2; c++) {
            int kb = c * 16;
            Bh[t][c][0] = packh(Whh[pr * 32 + kb + k0],     Whh[pr * 32 + kb + k0 + 1]);
            Bh[t][c][1] = packh(Whh[pr * 32 + kb + k0 + 8], Whh[pr * 32 + kb + k0 + 9]);
        }
        // x-chunk rows: 0-3 U (xhi), 4-7 U (xlo), 8-11 zero, 12 b_hi, 13 b_lo
        float xv[4];
#pragma unroll
        for (int q = 0; q < 4; q++) {
            int k = ((q < 2) ? k0 : k0 + 8) + (q & 1);
            float v = 0.0f;
            if (k < 4)       v = Wih[pr * 4 + k];
            else if (k < 8)  v = Wih[pr * 4 + k - 4];
            else if (k == 12) { float b = bih[pr] + bhh[pr]; v = h_round(b); }
            else if (k == 13) { float b = bih[pr] + bhh[pr]; v = b - h_round(b); }
            xv[q] = v;
        }
        Bx[t][0] = packh(xv[0], xv[1]);
        Bx[t][1] = packh(xv[2], xv[3]);
    }

    // ---------------- prime smem ----------------
    for (int i = tid; i < GSAMP * XH_STR; i += 128) {
        Xhi[0][i / XH_STR][i % XH_STR] = __float2half(0.0f);
    }
    if (tid < GSAMP) {
        const float4 x = ((const float4*)hist)[(size_t)(S0 + tid) * TSEQ];
        float h0 = h_round(x.x), h1 = h_round(x.y), h2 = h_round(x.z), h3 = h_round(x.w);
        uint4 q0, q1;
        q0.x = packh(x.x, x.y);           q0.y = packh(x.z, x.w);
        q0.z = packh(x.x - h0, x.y - h1); q0.w = packh(x.z - h2, x.w - h3);
        q1.x = 0u; q1.y = 0u;
        q1.z = packh(1.0f, 1.0f);         q1.w = 0u;
        ((uint4*)&Xx[0][tid][0])[0] = q0;
        ((uint4*)&Xx[0][tid][0])[1] = q1;
    }
    __syncthreads();

    // ldmatrix addressing (x4): lane -> matrix m = lane/8
    const int mrow  = (lane & 7) + ((lane >> 3) & 1) * 8;
    const int mkoff = ((lane >> 4) & 1) * 16;      // bytes
    const uint32_t aXhi = s2u(&Xhi[0][0][0]);
    const uint32_t aXx  = s2u(&Xx[0][0][0]);
    const uint32_t PAR_H = GSAMP * XH_STR * 2;     // parity stride bytes
    const uint32_t PAR_X = GSAMP * XX_STR * 2;

    const int r  = lane >> 2;                      // sample row (and r+8)
    const int u0 = 8 * w + j;                      // this lane's units
    const int u1 = u0 + 4;

    float cst[4];                                  // c for (u0,r),(u0,r+8),(u1,r),(u1,r+8)
#pragma unroll
    for (int q = 0; q < 4; q++) cst[q] = 0.0f;

    int p = 0;
    for (int step = 0; step < TSEQ + PSTEPS; step++) {
        const bool dec = (step >= TSEQ);

        // ---- decode boundary: rebuild B frags with fused weights ----
        if (step == TSEQ) {
#pragma unroll
            for (int t = 0; t < 4; t++) {
                int col = 32 * w + 8 * t + nsub;
                int pr  = prow(col);
#pragma unroll
                for (int c = 0; c < 2; c++) {
                    int kb = c * 16;
                    float wv[4];
#pragma unroll
                    for (int q = 0; q < 4; q++) {
                        int kk = kb + ((q < 2) ? k0 : k0 + 8) + (q & 1);
                        float v = Whh[pr * 32 + kk];
#pragma unroll
                        for (int d = 0; d < 4; d++)
                            v += Wih[pr * 4 + d] * Wpred[d * 32 + kk];
                        wv[q] = v;
                    }
                    Bh[t][c][0] = packh(wv[0], wv[1]);
                    Bh[t][c][1] = packh(wv[2], wv[3]);
                }
                float bd = bih[pr] + bhh[pr];
#pragma unroll
                for (int d = 0; d < 4; d++) bd += Wih[pr * 4 + d] * bpred[d];
                float xv[4];
#pragma unroll
                for (int q = 0; q < 4; q++) {
                    int k = ((q < 2) ? k0 : k0 + 8) + (q & 1);
                    xv[q] = (k == 12) ? h_round(bd) : (k == 13) ? (bd - h_round(bd)) : 0.0f;
                }
                Bx[t][0] = packh(xv[0], xv[1]);
                Bx[t][1] = packh(xv[2], xv[3]);
            }
            if (w == 3) {   // pred tile: cols = pred dims 0-3 (4-7 zero), Wpred hi/lo
                int d = nsub;
                bool ok = (d < 4);
#pragma unroll
                for (int c = 0; c < 2; c++) {
                    int kb = c * 16;
                    float w0 = ok ? Wpred[d * 32 + kb + k0]     : 0.0f;
                    float w1 = ok ? Wpred[d * 32 + kb + k0 + 1] : 0.0f;
                    float w8 = ok ? Wpred[d * 32 + kb + k0 + 8] : 0.0f;
                    float w9 = ok ? Wpred[d * 32 + kb + k0 + 9] : 0.0f;
                    Ph[c][0] = packh(w0, w1);
                    Ph[c][1] = packh(w8, w9);
                    Pl[c][0] = packh(w0 - h_round(w0), w1 - h_round(w1));
                    Pl[c][1] = packh(w8 - h_round(w8), w9 - h_round(w9));
                }
                float bp = ok ? bpred[d] : 0.0f;
                float xv[4];
#pragma unroll
                for (int q = 0; q < 4; q++) {
                    int k = ((q < 2) ? k0 : k0 + 8) + (q & 1);
                    xv[q] = (k == 12) ? h_round(bp) : (k == 13) ? (bp - h_round(bp)) : 0.0f;
                }
                Px[0] = packh(xv[0], xv[1]);
                Px[1] = packh(xv[2], xv[3]);
            }
        }

        // ---- load A fragments from staging (parity p) ----
        uint32_t Ah0[4], Ah1[4], Ax[4];
        {
            uint32_t ah = aXhi + (uint32_t)p * PAR_H + (uint32_t)mrow * (XH_STR * 2) + mkoff;
            uint32_t ax = aXx  + (uint32_t)p * PAR_X + (uint32_t)mrow * (XX_STR * 2) + mkoff;
            ldsm4(Ah0, ah); ldsm4(Ah1, ah + 32);
            ldsm4(Ax,  ax);
        }

        // ---- prefetch next encoder x ----
        float4 xn;
        const bool wantx = (!dec) && (step + 1 < TSEQ) && (w == 0) && (lane < GSAMP);
        if (wantx) xn = ((const float4*)hist)[(size_t)(S0 + lane) * TSEQ + step + 1];

        // ---- MMAs: G = h*W + x-chunk   (3 per tile) ----
        float dacc[4][4];
#pragma unroll
        for (int t = 0; t < 4; t++) {
#pragma unroll
            for (int e = 0; e < 4; e++) dacc[t][e] = 0.0f;
            mma16816(dacc[t], Ah0, Bh[t][0]);
            mma16816(dacc[t], Ah1, Bh[t][1]);
            mma16816(dacc[t], Ax,  Bx[t]);
        }
        if (dec && w == 3) {
            float dp[4] = {0.0f, 0.0f, 0.0f, 0.0f};
            mma16816(dp, Ah0, Ph[0]); mma16816(dp, Ah1, Ph[1]);
            mma16816(dp, Ah0, Pl[0]); mma16816(dp, Ah1, Pl[1]);
            mma16816(dp, Ax,  Px);
            if (j < 2) {   // lanes holding pred cols
                int ps = step - TSEQ;
                float2* o0 = (float2*)(out + (size_t)(S0 + r)     * (PSTEPS * 4) + ps * 4 + j * 2);
                float2* o1 = (float2*)(out + (size_t)(S0 + r + 8) * (PSTEPS * 4) + ps * 4 + j * 2);
                *o0 = make_float2(dp[0], dp[1]);
                *o1 = make_float2(dp[2], dp[3]);
            }
        }

        // ---- epilogue: shuffle-free, divergence-free activations ----
        float hs[4];
#pragma unroll
        for (int uu = 0; uu < 2; uu++) {
#pragma unroll
            for (int rr = 0; rr < 2; rr++) {
                float gi = dacc[2 * uu][2 * rr + 0];
                float gf = dacc[2 * uu][2 * rr + 1];
                float gg = dacc[2 * uu + 1][2 * rr + 0];
                float go = dacc[2 * uu + 1][2 * rr + 1];
                float si = sigmA(gi);
                float tg = tanhA(gg);
                float so = sigmA(go);
                int ci = 2 * uu + rr;
                float cn = dec ? (si * tg) : fmaf(sigmA(gf), cst[ci], si * tg);
                cst[ci] = cn;
                hs[ci] = so * tanhA(cn);
            }
        }
        Xhi[p ^ 1][r][u0]     = __float2half_rn(hs[0]);
        Xhi[p ^ 1][r + 8][u0] = __float2half_rn(hs[1]);
        Xhi[p ^ 1][r][u1]     = __float2half_rn(hs[2]);
        Xhi[p ^ 1][r + 8][u1] = __float2half_rn(hs[3]);

        if (wantx) {
            float h0 = h_round(xn.x), h1 = h_round(xn.y);
            float h2 = h_round(xn.z), h3 = h_round(xn.w);
            uint4 q0, q1;
            q0.x = packh(xn.x, xn.y);           q0.y = packh(xn.z, xn.w);
            q0.z = packh(xn.x - h0, xn.y - h1); q0.w = packh(xn.z - h2, xn.w - h3);
            q1.x = 0u; q1.y = 0u;
            q1.z = packh(1.0f, 1.0f);           q1.w = 0u;
            ((uint4*)&Xx[p ^ 1][lane][0])[0] = q0;
            ((uint4*)&Xx[p ^ 1][lane][0])[1] = q1;
        }

        __syncthreads();
        p ^= 1;
    }
}

extern "C" void kernel_launch(void* const* d_in, const int* in_sizes, int n_in,
                              void* d_out, int out_size) {
    const float* hist  = (const float*)d_in[0];
    const float* Wih   = (const float*)d_in[1];
    const float* Whh   = (const float*)d_in[2];
    const float* bih   = (const float*)d_in[3];
    const float* bhh   = (const float*)d_in[4];
    const float* Wpred = (const float*)d_in[5];
    const float* bpred = (const float*)d_in[6];
    lstm_hmma_kernel<<<NCTA, 128>>>(hist, Wih, Whh, bih, bhh, Wpred, bpred,
                                    (float*)d_out);
}

// round 12
// speedup vs baseline: 7.1288x; 1.0743x over previous
#include <cuda_runtime.h>
#include <cuda_fp16.h>
#include <cstdint>

#define TSEQ 200
#define PSTEPS 50
#define BATCHN 32768
#define GSAMP 16
#define NCTA (BATCHN / GSAMP)   // 2048
#define XH_STR 40               // f16 elems per row (80B, 16B aligned, conflict-free ldsm)
#define XX_STR 8                // 16B rows (k8 x-chunk)
#define H05 0x38003800u         // (0.5, 0.5) f16x2

// ---------------- helpers ----------------
__device__ __forceinline__ uint32_t s2u(const void* p) {
    uint32_t a;
    asm("{ .reg .u64 t; cvta.to.shared.u64 t, %1; cvt.u32.u64 %0, t; }" : "=r"(a) : "l"(p));
    return a;
}
__device__ __forceinline__ uint32_t packh(float a, float b) {  // (f16(a), f16(b))
    uint32_t r;
    asm("{.reg .b16 x,y; cvt.rn.f16.f32 x, %1; cvt.rn.f16.f32 y, %2; mov.b32 %0, {x,y};}"
        : "=r"(r) : "f"(a), "f"(b));
    return r;
}
// f16x2 with lo = first arg, hi = second
__device__ __forceinline__ uint32_t cvt2h(float lo, float hi) {
    uint32_t r; asm("cvt.rn.f16x2.f32 %0, %1, %2;" : "=r"(r) : "f"(hi), "f"(lo)); return r;
}
__device__ __forceinline__ uint32_t tanh2(uint32_t x) {
    uint32_t r; asm("tanh.approx.f16x2 %0, %1;" : "=r"(r) : "r"(x)); return r;
}
__device__ __forceinline__ uint32_t mul2(uint32_t a, uint32_t b) {
    uint32_t r; asm("mul.rn.f16x2 %0, %1, %2;" : "=r"(r) : "r"(a), "r"(b)); return r;
}
__device__ __forceinline__ uint32_t fma2h(uint32_t a, uint32_t b, uint32_t c) {
    uint32_t r; asm("fma.rn.f16x2 %0, %1, %2, %3;" : "=r"(r) : "r"(a), "r"(b), "r"(c)); return r;
}
__device__ __forceinline__ uint32_t sigm2(uint32_t g) {   // 0.5*tanh(0.5g)+0.5
    return fma2h(H05, tanh2(mul2(g, H05)), H05);
}
__device__ __forceinline__ void mma16816(float* d, const uint32_t* a, const uint32_t* b) {
    asm volatile("mma.sync.aligned.m16n8k16.row.col.f32.f16.f16.f32 "
                 "{%0,%1,%2,%3}, {%4,%5,%6,%7}, {%8,%9}, {%0,%1,%2,%3};"
                 : "+f"(d[0]), "+f"(d[1]), "+f"(d[2]), "+f"(d[3])
                 : "r"(a[0]), "r"(a[1]), "r"(a[2]), "r"(a[3]), "r"(b[0]), "r"(b[1]));
}
__device__ __forceinline__ void mma1688(float* d, const uint32_t* a, uint32_t b) {
    asm volatile("mma.sync.aligned.m16n8k8.row.col.f32.f16.f16.f32 "
                 "{%0,%1,%2,%3}, {%4,%5}, {%6}, {%0,%1,%2,%3};"
                 : "+f"(d[0]), "+f"(d[1]), "+f"(d[2]), "+f"(d[3])
                 : "r"(a[0]), "r"(a[1]), "r"(b));
}
__device__ __forceinline__ void ldsm4(uint32_t* r, uint32_t addr) {
    asm volatile("ldmatrix.sync.aligned.m8n8.x4.shared.b16 {%0,%1,%2,%3}, [%4];"
                 : "=r"(r[0]), "=r"(r[1]), "=r"(r[2]), "=r"(r[3]) : "r"(addr));
}
__device__ __forceinline__ void ldsm2(uint32_t* r, uint32_t addr) {
    asm volatile("ldmatrix.sync.aligned.m8n8.x2.shared.b16 {%0,%1}, [%2];"
                 : "=r"(r[0]), "=r"(r[1]) : "r"(addr));
}
__device__ __forceinline__ void sts_halves(uint32_t h2, uint32_t alo, uint32_t ahi) {
    asm volatile("{.reg .b16 lo,hi; mov.b32 {lo,hi}, %0; "
                 "st.shared.b16 [%1], lo; st.shared.b16 [%2], hi;}"
                 :: "r"(h2), "r"(alo), "r"(ahi));
}

// Shuffle-free gate-column map: lane j's four dacc tiles hold complete
// (i,f,g,o) for units 8w+j and 8w+j+4, rows r and r+8.
__device__ __forceinline__ int prow(int col) {
    int t  = (col >> 3) & 3;
    int jc = (col >> 1) & 3;
    int dj = col & 1;
    int u  = ((col >> 5) << 3) + jc + ((t >> 1) << 2);
    int blk = (t & 1) ? (dj ? 3 : 2) : (dj ? 1 : 0);   // i,f,g,o row blocks
    return blk * 32 + u;
}

__global__ void __launch_bounds__(128, 7) lstm_hmma_kernel(
    const float* __restrict__ hist,
    const float* __restrict__ Wih,
    const float* __restrict__ Whh,
    const float* __restrict__ bih,
    const float* __restrict__ bhh,
    const float* __restrict__ Wpred,
    const float* __restrict__ bpred,
    float* __restrict__ out)
{
    __shared__ __align__(16) __half Xhi[2][GSAMP][XH_STR];
    __shared__ __align__(16) __half Xx [2][GSAMP][XX_STR];

    const int tid  = threadIdx.x;
    const int lane = tid & 31;
    const int w    = tid >> 5;
    const int S0   = blockIdx.x * GSAMP;

    const int j    = lane & 3;
    const int nsub = lane >> 2;
    const int k0   = 2 * j;

    uint32_t Bh[4][2][2], Bx[4];          // Whh f16; x-chunk k8 (Wih | bias)
    uint32_t Ph[2][2], Px;                // warp3 pred tile (decode), f16 single

#pragma unroll
    for (int t = 0; t < 4; t++) {
        int col = 32 * w + 8 * t + nsub;
        int pr  = prow(col);
#pragma unroll
        for (int c = 0; c < 2; c++) {
            int kb = c * 16;
            Bh[t][c][0] = packh(Whh[pr * 32 + kb + k0],     Whh[pr * 32 + kb + k0 + 1]);
            Bh[t][c][1] = packh(Whh[pr * 32 + kb + k0 + 8], Whh[pr * 32 + kb + k0 + 9]);
        }
        // x-chunk (k8): rows 0-3 = Wih cols, row 4 = bias (A row 4 = ones)
        float v0 = 0.0f, v1 = 0.0f;
        if (j == 0)      { v0 = Wih[pr * 4 + 0]; v1 = Wih[pr * 4 + 1]; }
        else if (j == 1) { v0 = Wih[pr * 4 + 2]; v1 = Wih[pr * 4 + 3]; }
        else if (j == 2) { v0 = bih[pr] + bhh[pr]; }
        Bx[t] = packh(v0, v1);
    }

    // ---------------- prime smem ----------------
    for (int i = tid; i < GSAMP * XH_STR; i += 128) {
        Xhi[0][i / XH_STR][i % XH_STR] = __float2half(0.0f);
    }
    if (tid < GSAMP) {
        const float4 x = ((const float4*)hist)[(size_t)(S0 + tid) * TSEQ];
        uint4 q;
        q.x = packh(x.x, x.y); q.y = packh(x.z, x.w);
        q.z = packh(1.0f, 0.0f); q.w = 0u;
        ((uint4*)&Xx[0][tid][0])[0] = q;
    }
    __syncthreads();

    // ldmatrix addressing
    const int mrow  = (lane & 7) + ((lane >> 3) & 1) * 8;
    const int mkoff = ((lane >> 4) & 1) * 16;      // bytes (Xhi x4 only)
    const uint32_t aXhi = s2u(&Xhi[0][0][0]);
    const uint32_t aXx  = s2u(&Xx[0][0][0]);
    const uint32_t PAR_H = GSAMP * XH_STR * 2;     // parity stride bytes
    const uint32_t PAR_X = GSAMP * XX_STR * 2;     // 256B

    const int r  = lane >> 2;                      // sample row (and r+8)
    const int u0 = 8 * w + j;                      // this lane's units
    const int u1 = u0 + 4;

    uint32_t cst2[2] = {0u, 0u};                   // c as f16x2 (rows r, r+8) per unit

    int p = 0;
    for (int step = 0; step < TSEQ + PSTEPS; step++) {
        const bool dec = (step >= TSEQ);

        // ---- decode boundary: rebuild B frags with fused weights ----
        if (step == TSEQ) {
#pragma unroll
            for (int t = 0; t < 4; t++) {
                int col = 32 * w + 8 * t + nsub;
                int pr  = prow(col);
#pragma unroll
                for (int c = 0; c < 2; c++) {
                    int kb = c * 16;
                    float wv[4];
#pragma unroll
                    for (int q = 0; q < 4; q++) {
                        int kk = kb + ((q < 2) ? k0 : k0 + 8) + (q & 1);
                        float v = Whh[pr * 32 + kk];
#pragma unroll
                        for (int d = 0; d < 4; d++)
                            v += Wih[pr * 4 + d] * Wpred[d * 32 + kk];
                        wv[q] = v;
                    }
                    Bh[t][c][0] = packh(wv[0], wv[1]);
                    Bh[t][c][1] = packh(wv[2], wv[3]);
                }
                float bd = 0.0f;
                if (j == 2) {
                    bd = bih[pr] + bhh[pr];
#pragma unroll
                    for (int d = 0; d < 4; d++) bd += Wih[pr * 4 + d] * bpred[d];
                }
                Bx[t] = packh(bd, 0.0f);           // x rows now zero; row4 = fused bias
            }
            if (w == 3) {   // pred tile: cols = pred dims 0-3 (4-7 zero)
                int d = nsub;
                bool ok = (d < 4);
#pragma unroll
                for (int c = 0; c < 2; c++) {
                    int kb = c * 16;
                    Ph[c][0] = packh(ok ? Wpred[d * 32 + kb + k0]     : 0.0f,
                                     ok ? Wpred[d * 32 + kb + k0 + 1] : 0.0f);
                    Ph[c][1] = packh(ok ? Wpred[d * 32 + kb + k0 + 8] : 0.0f,
                                     ok ? Wpred[d * 32 + kb + k0 + 9] : 0.0f);
                }
                Px = packh((j == 2 && ok) ? bpred[d] : 0.0f, 0.0f);
            }
        }

        // ---- load A fragments from staging (parity p) ----
        uint32_t Ah0[4], Ah1[4], Ax[2];
        {
            uint32_t ah = aXhi + (uint32_t)p * PAR_H + (uint32_t)mrow * (XH_STR * 2) + mkoff;
            uint32_t ax = aXx  + (uint32_t)p * PAR_X + (uint32_t)(lane & 15) * (XX_STR * 2);
            ldsm4(Ah0, ah); ldsm4(Ah1, ah + 32);
            ldsm2(Ax, ax);
        }

        // ---- prefetch next encoder x ----
        float4 xn;
        const bool wantx = (!dec) && (step + 1 < TSEQ) && (w == 0) && (lane < GSAMP);
        if (wantx) xn = ((const float4*)hist)[(size_t)(S0 + lane) * TSEQ + step + 1];

        // ---- MMAs: G = h*W + x-chunk   (2x k16 + 1x k8 per tile) ----
        float dacc[4][4];
#pragma unroll
        for (int t = 0; t < 4; t++) {
#pragma unroll
            for (int e = 0; e < 4; e++) dacc[t][e] = 0.0f;
            mma16816(dacc[t], Ah0, Bh[t][0]);
            mma16816(dacc[t], Ah1, Bh[t][1]);
            mma1688(dacc[t], Ax, Bx[t]);
        }
        if (dec && w == 3) {
            float dp[4] = {0.0f, 0.0f, 0.0f, 0.0f};
            mma16816(dp, Ah0, Ph[0]);
            mma16816(dp, Ah1, Ph[1]);
            mma1688(dp, Ax, Px);
            if (j < 2) {   // lanes holding pred cols
                int ps = step - TSEQ;
                float2* o0 = (float2*)(out + (size_t)(S0 + r)     * (PSTEPS * 4) + ps * 4 + j * 2);
                float2* o1 = (float2*)(out + (size_t)(S0 + r + 8) * (PSTEPS * 4) + ps * 4 + j * 2);
                *o0 = make_float2(dp[0], dp[1]);
                *o1 = make_float2(dp[2], dp[3]);
            }
        }

        // ---- epilogue: f16x2 SIMD activations (rows r, r+8 as one pair) ----
        const uint32_t hbase = aXhi + (uint32_t)(p ^ 1) * PAR_H;
#pragma unroll
        for (int uu = 0; uu < 2; uu++) {
            uint32_t gi2 = cvt2h(dacc[2 * uu][0],     dacc[2 * uu][2]);
            uint32_t gf2 = cvt2h(dacc[2 * uu][1],     dacc[2 * uu][3]);
            uint32_t gg2 = cvt2h(dacc[2 * uu + 1][0], dacc[2 * uu + 1][2]);
            uint32_t go2 = cvt2h(dacc[2 * uu + 1][1], dacc[2 * uu + 1][3]);
            uint32_t si2 = sigm2(gi2);
            uint32_t tg2 = tanh2(gg2);
            uint32_t so2 = sigm2(go2);
            uint32_t itg = mul2(si2, tg2);
            uint32_t cn2 = dec ? itg : fma2h(sigm2(gf2), cst2[uu], itg);
            cst2[uu] = cn2;
            uint32_t h2 = mul2(so2, tanh2(cn2));
            int u = (uu == 0) ? u0 : u1;
            uint32_t alo = hbase + (uint32_t)(r * XH_STR + u) * 2u;
            sts_halves(h2, alo, alo + 8u * XH_STR * 2u);
        }

        if (wantx) {
            uint4 q;
            q.x = packh(xn.x, xn.y); q.y = packh(xn.z, xn.w);
            q.z = packh(1.0f, 0.0f); q.w = 0u;
            ((uint4*)&Xx[p ^ 1][lane][0])[0] = q;
        }

        __syncthreads();
        p ^= 1;
    }
}

extern "C" void kernel_launch(void* const* d_in, const int* in_sizes, int n_in,
                              void* d_out, int out_size) {
    const float* hist  = (const float*)d_in[0];
    const float* Wih   = (const float*)d_in[1];
    const float* Whh   = (const float*)d_in[2];
    const float* bih   = (const float*)d_in[3];
    const float* bhh   = (const float*)d_in[4];
    const float* Wpred = (const float*)d_in[5];
    const float* bpred = (const float*)d_in[6];
    lstm_hmma_kernel<<<NCTA, 128>>>(hist, Wih, Whh, bih, bhh, Wpred, bpred,
                                    (float*)d_out);
}

// round 13
// speedup vs baseline: 7.7040x; 1.0807x over previous
#include <cuda_runtime.h>
#include <cuda_fp16.h>
#include <cstdint>

#define TSEQ 200
#define PSTEPS 50
#define BATCHN 32768
#define GSAMP 16
#define NCTA (BATCHN / GSAMP)   // 2048
#define XH_STR 40               // f16 elems per row (80B, 16B aligned, conflict-free ldsm)
#define XX_STR 8                // 16B rows (k8 x-chunk)
#define H05 0x38003800u         // (0.5, 0.5) f16x2

// ---------------- helpers ----------------
__device__ __forceinline__ uint32_t s2u(const void* p) {
    uint32_t a;
    asm("{ .reg .u64 t; cvta.to.shared.u64 t, %1; cvt.u32.u64 %0, t; }" : "=r"(a) : "l"(p));
    return a;
}
__device__ __forceinline__ uint32_t packh(float a, float b) {  // (f16(a), f16(b))
    uint32_t r;
    asm("{.reg .b16 x,y; cvt.rn.f16.f32 x, %1; cvt.rn.f16.f32 y, %2; mov.b32 %0, {x,y};}"
        : "=r"(r) : "f"(a), "f"(b));
    return r;
}
__device__ __forceinline__ uint32_t tanh2(uint32_t x) {
    uint32_t r; asm("tanh.approx.f16x2 %0, %1;" : "=r"(r) : "r"(x)); return r;
}
__device__ __forceinline__ uint32_t mul2(uint32_t a, uint32_t b) {
    uint32_t r; asm("mul.rn.f16x2 %0, %1, %2;" : "=r"(r) : "r"(a), "r"(b)); return r;
}
__device__ __forceinline__ uint32_t fma2h(uint32_t a, uint32_t b, uint32_t c) {
    uint32_t r; asm("fma.rn.f16x2 %0, %1, %2, %3;" : "=r"(r) : "r"(a), "r"(b), "r"(c)); return r;
}
__device__ __forceinline__ uint32_t sigm2(uint32_t g) {   // 0.5*tanh(0.5g)+0.5
    return fma2h(H05, tanh2(mul2(g, H05)), H05);
}
__device__ __forceinline__ uint32_t prmt(uint32_t a, uint32_t b, uint32_t c) {
    uint32_t r; asm("prmt.b32 %0, %1, %2, %3;" : "=r"(r) : "r"(a), "r"(b), "r"(c)); return r;
}
// f16-accumulator gate MMAs (d = 2x f16x2: {c0,c1}@r, {c0,c1}@r+8)
__device__ __forceinline__ void mma16816h(uint32_t* d, const uint32_t* a, const uint32_t* b) {
    asm volatile("mma.sync.aligned.m16n8k16.row.col.f16.f16.f16.f16 "
                 "{%0,%1}, {%2,%3,%4,%5}, {%6,%7}, {%0,%1};"
                 : "+r"(d[0]), "+r"(d[1])
                 : "r"(a[0]), "r"(a[1]), "r"(a[2]), "r"(a[3]), "r"(b[0]), "r"(b[1]));
}
__device__ __forceinline__ void mma1688h(uint32_t* d, const uint32_t* a, uint32_t b) {
    asm volatile("mma.sync.aligned.m16n8k8.row.col.f16.f16.f16.f16 "
                 "{%0,%1}, {%2,%3}, {%4}, {%0,%1};"
                 : "+r"(d[0]), "+r"(d[1])
                 : "r"(a[0]), "r"(a[1]), "r"(b));
}
// f32-accumulator MMAs (pred output path only — error there is undamped)
__device__ __forceinline__ void mma16816(float* d, const uint32_t* a, const uint32_t* b) {
    asm volatile("mma.sync.aligned.m16n8k16.row.col.f32.f16.f16.f32 "
                 "{%0,%1,%2,%3}, {%4,%5,%6,%7}, {%8,%9}, {%0,%1,%2,%3};"
                 : "+f"(d[0]), "+f"(d[1]), "+f"(d[2]), "+f"(d[3])
                 : "r"(a[0]), "r"(a[1]), "r"(a[2]), "r"(a[3]), "r"(b[0]), "r"(b[1]));
}
__device__ __forceinline__ void mma1688(float* d, const uint32_t* a, uint32_t b) {
    asm volatile("mma.sync.aligned.m16n8k8.row.col.f32.f16.f16.f32 "
                 "{%0,%1,%2,%3}, {%4,%5}, {%6}, {%0,%1,%2,%3};"
                 : "+f"(d[0]), "+f"(d[1]), "+f"(d[2]), "+f"(d[3])
                 : "r"(a[0]), "r"(a[1]), "r"(b));
}
__device__ __forceinline__ void ldsm4(uint32_t* r, uint32_t addr) {
    asm volatile("ldmatrix.sync.aligned.m8n8.x4.shared.b16 {%0,%1,%2,%3}, [%4];"
                 : "=r"(r[0]), "=r"(r[1]), "=r"(r[2]), "=r"(r[3]) : "r"(addr));
}
__device__ __forceinline__ void ldsm2(uint32_t* r, uint32_t addr) {
    asm volatile("ldmatrix.sync.aligned.m8n8.x2.shared.b16 {%0,%1}, [%2];"
                 : "=r"(r[0]), "=r"(r[1]) : "r"(addr));
}
__device__ __forceinline__ void sts_halves(uint32_t h2, uint32_t alo, uint32_t ahi) {
    asm volatile("{.reg .b16 lo,hi; mov.b32 {lo,hi}, %0; "
                 "st.shared.b16 [%1], lo; st.shared.b16 [%2], hi;}"
                 :: "r"(h2), "r"(alo), "r"(ahi));
}

// Shuffle-free gate-column map: lane j's four gate tiles hold complete
// (i,f,g,o) for units 8w+j and 8w+j+4, rows r and r+8.
__device__ __forceinline__ int prow(int col) {
    int t  = (col >> 3) & 3;
    int jc = (col >> 1) & 3;
    int dj = col & 1;
    int u  = ((col >> 5) << 3) + jc + ((t >> 1) << 2);
    int blk = (t & 1) ? (dj ? 3 : 2) : (dj ? 1 : 0);   // i,f,g,o row blocks
    return blk * 32 + u;
}

__global__ void __launch_bounds__(128, 7) lstm_hmma_kernel(
    const float* __restrict__ hist,
    const float* __restrict__ Wih,
    const float* __restrict__ Whh,
    const float* __restrict__ bih,
    const float* __restrict__ bhh,
    const float* __restrict__ Wpred,
    const float* __restrict__ bpred,
    float* __restrict__ out)
{
    __shared__ __align__(16) __half Xhi[2][GSAMP][XH_STR];
    __shared__ __align__(16) __half Xx [2][GSAMP][XX_STR];

    const int tid  = threadIdx.x;
    const int lane = tid & 31;
    const int w    = tid >> 5;
    const int S0   = blockIdx.x * GSAMP;

    const int j    = lane & 3;
    const int nsub = lane >> 2;
    const int k0   = 2 * j;

    uint32_t Bh[4][2][2], Bx[4];          // Whh f16; x-chunk k8 (Wih | bias)
    uint32_t Ph[2][2], Px;                // warp3 pred tile (decode), f16 single

#pragma unroll
    for (int t = 0; t < 4; t++) {
        int col = 32 * w + 8 * t + nsub;
        int pr  = prow(col);
#pragma unroll
        for (int c = 0; c < 2; c++) {
            int kb = c * 16;
            Bh[t][c][0] = packh(Whh[pr * 32 + kb + k0],     Whh[pr * 32 + kb + k0 + 1]);
            Bh[t][c][1] = packh(Whh[pr * 32 + kb + k0 + 8], Whh[pr * 32 + kb + k0 + 9]);
        }
        // x-chunk (k8): rows 0-3 = Wih cols, row 4 = bias (A row 4 = ones)
        float v0 = 0.0f, v1 = 0.0f;
        if (j == 0)      { v0 = Wih[pr * 4 + 0]; v1 = Wih[pr * 4 + 1]; }
        else if (j == 1) { v0 = Wih[pr * 4 + 2]; v1 = Wih[pr * 4 + 3]; }
        else if (j == 2) { v0 = bih[pr] + bhh[pr]; }
        Bx[t] = packh(v0, v1);
    }

    // ---------------- prime smem ----------------
    for (int i = tid; i < GSAMP * XH_STR; i += 128) {
        Xhi[0][i / XH_STR][i % XH_STR] = __float2half(0.0f);
    }
    if (tid < GSAMP) {
        const float4 x = ((const float4*)hist)[(size_t)(S0 + tid) * TSEQ];
        uint4 q;
        q.x = packh(x.x, x.y); q.y = packh(x.z, x.w);
        q.z = packh(1.0f, 0.0f); q.w = 0u;
        ((uint4*)&Xx[0][tid][0])[0] = q;
    }
    __syncthreads();

    // ldmatrix addressing
    const int mrow  = (lane & 7) + ((lane >> 3) & 1) * 8;
    const int mkoff = ((lane >> 4) & 1) * 16;      // bytes (Xhi x4 only)
    const uint32_t aXhi = s2u(&Xhi[0][0][0]);
    const uint32_t aXx  = s2u(&Xx[0][0][0]);
    const uint32_t PAR_H = GSAMP * XH_STR * 2;     // parity stride bytes
    const uint32_t PAR_X = GSAMP * XX_STR * 2;     // 256B

    const int r  = lane >> 2;                      // sample row (and r+8)
    const int u0 = 8 * w + j;                      // this lane's units
    const int u1 = u0 + 4;

    uint32_t cst2[2] = {0u, 0u};                   // c as f16x2 (rows r, r+8) per unit

    int p = 0;
    for (int step = 0; step < TSEQ + PSTEPS; step++) {
        const bool dec = (step >= TSEQ);

        // ---- decode boundary: rebuild B frags with fused weights ----
        if (step == TSEQ) {
#pragma unroll
            for (int t = 0; t < 4; t++) {
                int col = 32 * w + 8 * t + nsub;
                int pr  = prow(col);
#pragma unroll
                for (int c = 0; c < 2; c++) {
                    int kb = c * 16;
                    float wv[4];
#pragma unroll
                    for (int q = 0; q < 4; q++) {
                        int kk = kb + ((q < 2) ? k0 : k0 + 8) + (q & 1);
                        float v = Whh[pr * 32 + kk];
#pragma unroll
                        for (int d = 0; d < 4; d++)
                            v += Wih[pr * 4 + d] * Wpred[d * 32 + kk];
                        wv[q] = v;
                    }
                    Bh[t][c][0] = packh(wv[0], wv[1]);
                    Bh[t][c][1] = packh(wv[2], wv[3]);
                }
                float bd = 0.0f;
                if (j == 2) {
                    bd = bih[pr] + bhh[pr];
#pragma unroll
                    for (int d = 0; d < 4; d++) bd += Wih[pr * 4 + d] * bpred[d];
                }
                Bx[t] = packh(bd, 0.0f);           // x rows now zero; row4 = fused bias
            }
            if (w == 3) {   // pred tile: cols = pred dims 0-3 (4-7 zero)
                int d = nsub;
                bool ok = (d < 4);
#pragma unroll
                for (int c = 0; c < 2; c++) {
                    int kb = c * 16;
                    Ph[c][0] = packh(ok ? Wpred[d * 32 + kb + k0]     : 0.0f,
                                     ok ? Wpred[d * 32 + kb + k0 + 1] : 0.0f);
                    Ph[c][1] = packh(ok ? Wpred[d * 32 + kb + k0 + 8] : 0.0f,
                                     ok ? Wpred[d * 32 + kb + k0 + 9] : 0.0f);
                }
                Px = packh((j == 2 && ok) ? bpred[d] : 0.0f, 0.0f);
            }
        }

        // ---- load A fragments from staging (parity p) ----
        uint32_t Ah0[4], Ah1[4], Ax[2];
        {
            uint32_t ah = aXhi + (uint32_t)p * PAR_H + (uint32_t)mrow * (XH_STR * 2) + mkoff;
            uint32_t ax = aXx  + (uint32_t)p * PAR_X + (uint32_t)(lane & 15) * (XX_STR * 2);
            ldsm4(Ah0, ah); ldsm4(Ah1, ah + 32);
            ldsm2(Ax, ax);
        }

        // ---- prefetch next encoder x ----
        float4 xn;
        const bool wantx = (!dec) && (step + 1 < TSEQ) && (w == 0) && (lane < GSAMP);
        if (wantx) xn = ((const float4*)hist)[(size_t)(S0 + lane) * TSEQ + step + 1];

        // ---- gate MMAs in f16 accum: G = h*W + x-chunk ----
        uint32_t dg[4][2];
#pragma unroll
        for (int t = 0; t < 4; t++) {
            dg[t][0] = 0u; dg[t][1] = 0u;
            mma16816h(dg[t], Ah0, Bh[t][0]);
            mma16816h(dg[t], Ah1, Bh[t][1]);
            mma1688h(dg[t], Ax, Bx[t]);
        }
        if (dec && w == 3) {   // pred in f32 accum (direct-to-output precision)
            float dp[4] = {0.0f, 0.0f, 0.0f, 0.0f};
            mma16816(dp, Ah0, Ph[0]);
            mma16816(dp, Ah1, Ph[1]);
            mma1688(dp, Ax, Px);
            if (j < 2) {
                int ps = step - TSEQ;
                float2* o0 = (float2*)(out + (size_t)(S0 + r)     * (PSTEPS * 4) + ps * 4 + j * 2);
                float2* o1 = (float2*)(out + (size_t)(S0 + r + 8) * (PSTEPS * 4) + ps * 4 + j * 2);
                *o0 = make_float2(dp[0], dp[1]);
                *o1 = make_float2(dp[2], dp[3]);
            }
        }

        // ---- epilogue: PRMT row-repack + f16x2 SIMD activations ----
        // dg[T][0] = (c0,c1)@r, dg[T][1] = (c0,c1)@r+8; even tile cols = (i,f),
        // odd tile cols = (g,o). Repack to (val@r, val@r+8) pairs.
        const uint32_t hbase = aXhi + (uint32_t)(p ^ 1) * PAR_H;
#pragma unroll
        for (int uu = 0; uu < 2; uu++) {
            uint32_t i2 = prmt(dg[2 * uu][0],     dg[2 * uu][1],     0x5410u);
            uint32_t f2 = prmt(dg[2 * uu][0],     dg[2 * uu][1],     0x7632u);
            uint32_t g2 = prmt(dg[2 * uu + 1][0], dg[2 * uu + 1][1], 0x5410u);
            uint32_t o2 = prmt(dg[2 * uu + 1][0], dg[2 * uu + 1][1], 0x7632u);
            uint32_t si2 = sigm2(i2);
            uint32_t tg2 = tanh2(g2);
            uint32_t so2 = sigm2(o2);
            uint32_t itg = mul2(si2, tg2);
            uint32_t cn2 = dec ? itg : fma2h(sigm2(f2), cst2[uu], itg);
            cst2[uu] = cn2;
            uint32_t h2 = mul2(so2, tanh2(cn2));
            int u = (uu == 0) ? u0 : u1;
            uint32_t alo = hbase + (uint32_t)(r * XH_STR + u) * 2u;
            sts_halves(h2, alo, alo + 8u * XH_STR * 2u);
        }

        if (wantx) {
            uint4 q;
            q.x = packh(xn.x, xn.y); q.y = packh(xn.z, xn.w);
            q.z = packh(1.0f, 0.0f); q.w = 0u;
            ((uint4*)&Xx[p ^ 1][lane][0])[0] = q;
        }

        __syncthreads();
        p ^= 1;
    }
}

extern "C" void kernel_launch(void* const* d_in, const int* in_sizes, int n_in,
                              void* d_out, int out_size) {
    const float* hist  = (const float*)d_in[0];
    const float* Wih   = (const float*)d_in[1];
    const float* Whh   = (const float*)d_in[2];
    const float* bih   = (const float*)d_in[3];
    const float* bhh   = (const float*)d_in[4];
    const float* Wpred = (const float*)d_in[5];
    const float* bpred = (const float*)d_in[6];
    lstm_hmma_kernel<<<NCTA, 128>>>(hist, Wih, Whh, bih, bhh, Wpred, bpred,
                                    (float*)d_out);
}